// round 14
// baseline (speedup 1.0000x reference)
#include <cuda_runtime.h>
#include <cuda_bf16.h>
#include <math.h>
#include <stdint.h>

#define BB 2
#define SS 2048
#define DD 1024
#define HH 16
#define MROWS (BB*SS)   // 4096
#define KP 3072         // 3*K split depth

// ---------------- scratch (no cudaMalloc allowed) ----------------
__device__ float g_y[(size_t)MROWS * DD];
__device__ int   g_mask_mode;
__device__ __align__(8) unsigned int g_maskbits[(size_t)BB * SS * SS / 32];
__device__ __nv_bfloat16 g_x3[(size_t)MROWS * KP];
__device__ __nv_bfloat16 g_at3[(size_t)MROWS * KP];
__device__ __nv_bfloat16 g_wa3[(size_t)KP * 3072];
__device__ __nv_bfloat16 g_wo3[(size_t)KP * 1024];
#define HSZ ((size_t)BB * HH * SS * 64)
__device__ __nv_bfloat16 g_Qhi[HSZ], g_Qlo[HSZ];
__device__ __nv_bfloat16 g_Khi[HSZ], g_Klo[HSZ];
__device__ __nv_bfloat16 g_Vhi[HSZ], g_Vlo[HSZ];

// ---------------- mask dtype detection ----------------
__global__ void detect_mask_kernel(const unsigned int* __restrict__ m)
{
    __shared__ int sfloat, shigh;
    if (threadIdx.x == 0) { sfloat = 0; shigh = 0; }
    __syncthreads();
    int ff = 0, fh = 0;
    for (int i = threadIdx.x; i < 65536; i += blockDim.x) {
        unsigned int w = m[i];
        if (w == 0x3F800000u) ff = 1;
        else if (w & 0xFFFFFF00u) fh = 1;
    }
    if (ff) atomicOr(&sfloat, 1);
    if (fh) atomicOr(&shigh, 1);
    __syncthreads();
    if (threadIdx.x == 0)
        g_mask_mode = sfloat ? 2 : (shigh ? 1 : 0);
}

__global__ __launch_bounds__(256)
void convert_mask_kernel(const unsigned char* __restrict__ mb)
{
    const int mode = g_mask_mode;
    const int stride = (mode == 1) ? 1 : 4;
    const int offs   = (mode == 2) ? 3 : 0;
    size_t pos = (size_t)blockIdx.x * blockDim.x + threadIdx.x;
    unsigned char v = mb[pos * stride + offs];
    unsigned int bal = __ballot_sync(0xffffffffu, v != 0);
    if ((threadIdx.x & 31) == 0) g_maskbits[pos >> 5] = bal;
}

// ---------------- fp32 -> bf16x3 split conversions ----------------
__global__ __launch_bounds__(256)
void cvt_A3(const float* __restrict__ A, __nv_bfloat16* __restrict__ out, int K)
{
    size_t i = ((size_t)blockIdx.x * 256 + threadIdx.x) * 4;
    int m = (int)(i / K), k = (int)(i % K);
    float4 v = *(const float4*)(A + i);
    __nv_bfloat16 h[4], l[4];
    h[0] = __float2bfloat16_rn(v.x); l[0] = __float2bfloat16_rn(v.x - __bfloat162float(h[0]));
    h[1] = __float2bfloat16_rn(v.y); l[1] = __float2bfloat16_rn(v.y - __bfloat162float(h[1]));
    h[2] = __float2bfloat16_rn(v.z); l[2] = __float2bfloat16_rn(v.z - __bfloat162float(h[2]));
    h[3] = __float2bfloat16_rn(v.w); l[3] = __float2bfloat16_rn(v.w - __bfloat162float(h[3]));
    __nv_bfloat16* row = out + (size_t)m * (3 * K);
    *(uint2*)(row + k)         = *(uint2*)h;
    *(uint2*)(row + K + k)     = *(uint2*)l;
    *(uint2*)(row + 2 * K + k) = *(uint2*)h;
}

__global__ __launch_bounds__(256)
void cvt_B3(const float* __restrict__ B, __nv_bfloat16* __restrict__ out, int K, int N)
{
    size_t i = ((size_t)blockIdx.x * 256 + threadIdx.x) * 4;
    if (i >= (size_t)K * N) return;
    int r = (int)(i / N), c = (int)(i % N);
    float4 v = *(const float4*)(B + i);
    __nv_bfloat16 h[4], l[4];
    h[0] = __float2bfloat16_rn(v.x); l[0] = __float2bfloat16_rn(v.x - __bfloat162float(h[0]));
    h[1] = __float2bfloat16_rn(v.y); l[1] = __float2bfloat16_rn(v.y - __bfloat162float(h[1]));
    h[2] = __float2bfloat16_rn(v.z); l[2] = __float2bfloat16_rn(v.z - __bfloat162float(h[2]));
    h[3] = __float2bfloat16_rn(v.w); l[3] = __float2bfloat16_rn(v.w - __bfloat162float(h[3]));
    *(uint2*)(out + (size_t)r * N + c)           = *(uint2*)h;
    *(uint2*)(out + (size_t)(K + r) * N + c)     = *(uint2*)h;
    *(uint2*)(out + (size_t)(2 * K + r) * N + c) = *(uint2*)l;
}

// ---------------- MMA / cp.async macros ----------------
#define LDMX4(R0,R1,R2,R3,addr) \
    asm volatile("ldmatrix.sync.aligned.m8n8.x4.shared.b16 {%0,%1,%2,%3}, [%4];" \
        : "=r"(R0),"=r"(R1),"=r"(R2),"=r"(R3) : "r"(addr))
#define LDMX4T(R0,R1,R2,R3,addr) \
    asm volatile("ldmatrix.sync.aligned.m8n8.x4.trans.shared.b16 {%0,%1,%2,%3}, [%4];" \
        : "=r"(R0),"=r"(R1),"=r"(R2),"=r"(R3) : "r"(addr))
#define MMA16816(d, a, b0, b1) \
    asm volatile("mma.sync.aligned.m16n8k16.row.col.f32.bf16.bf16.f32 " \
        "{%0,%1,%2,%3}, {%4,%5,%6,%7}, {%8,%9}, {%0,%1,%2,%3};" \
        : "+f"(d[0]),"+f"(d[1]),"+f"(d[2]),"+f"(d[3]) \
        : "r"(a[0]),"r"(a[1]),"r"(a[2]),"r"(a[3]), "r"(b0),"r"(b1))
#define CPA16(saddr, gptr) \
    asm volatile("cp.async.cg.shared.global [%0], [%1], 16;" :: "r"(saddr), "l"(gptr))
#define CPA8(saddr, gptr) \
    asm volatile("cp.async.ca.shared.global [%0], [%1], 8;" :: "r"(saddr), "l"(gptr))
#define CPA_COMMIT() asm volatile("cp.async.commit_group;")
#define CPA_WAIT1()  asm volatile("cp.async.wait_group 1;")
#define CPA_WAIT0()  asm volatile("cp.async.wait_group 0;")

__device__ __forceinline__ uint32_t pack_bf2(float a, float b) {
    __nv_bfloat162 t = __floats2bfloat162_rn(a, b);
    return *(uint32_t*)&t;
}
__device__ __forceinline__ uint32_t pack_lo2(float a, float b) {
    float ha = __bfloat162float(__float2bfloat16_rn(a));
    float hb = __bfloat162float(__float2bfloat16_rn(b));
    return pack_bf2(a - ha, b - hb);
}

// ---------------- bf16 tensor-core GEMM, 3-stage cp.async pipeline ----------------
// EPI=0: epilogue stages per-head Q/K/V hi/lo split through smem (QKV proj)
// EPI=1: epilogue writes fp32 C with bias + residual (out proj)
#define STAGE_B 18944            // As 128x40x2 (10240) + Bs 32x136x2 (8704)
#define GEMM_SMEM (3*STAGE_B)    // 56832

template<int EPI>
__global__ __launch_bounds__(256)
void gemm_bf16(const __nv_bfloat16* __restrict__ A, const __nv_bfloat16* __restrict__ B,
               const float* __restrict__ bias, const float* __restrict__ resid,
               float* __restrict__ C, int M, int N, int Kp)
{
    __shared__ __align__(16) char smraw[GEMM_SMEM];
    const uint32_t smem_u = (uint32_t)__cvta_generic_to_shared(smraw);

    const int tid  = threadIdx.x;
    const int lane = tid & 31;
    const int wid  = tid >> 5;
    const int wm   = wid & 3;
    const int wn   = wid >> 2;
    const int bm = blockIdx.y * 128, bn = blockIdx.x * 128;

    const int a_chunk = tid & 3;
    const int a_row   = tid >> 2;
    const int b_chunk = tid & 15;
    const int b_row   = tid >> 4;

    // per-thread smem dst offsets (within one stage)
    const uint32_t a_off0 = (uint32_t)(a_row * 80 + a_chunk * 16);
    const uint32_t a_off1 = (uint32_t)((a_row + 64) * 80 + a_chunk * 16);
    const uint32_t b_off0 = (uint32_t)(10240 + b_row * 272 + b_chunk * 16);
    const uint32_t b_off1 = (uint32_t)(10240 + (b_row + 16) * 272 + b_chunk * 16);
    // per-thread gmem src bases
    const __nv_bfloat16* a_g0 = A + (size_t)(bm + a_row) * Kp + a_chunk * 8;
    const __nv_bfloat16* a_g1 = A + (size_t)(bm + a_row + 64) * Kp + a_chunk * 8;
    const __nv_bfloat16* b_g0 = B + (size_t)b_row * N + bn + b_chunk * 8;
    const __nv_bfloat16* b_g1 = B + (size_t)(b_row + 16) * N + bn + b_chunk * 8;

    auto issue = [&](int c) {
        const uint32_t st = smem_u + (uint32_t)((c % 3) * STAGE_B);
        const int k0 = c << 5;
        CPA16(st + a_off0, a_g0 + k0);
        CPA16(st + a_off1, a_g1 + k0);
        CPA16(st + b_off0, b_g0 + (size_t)k0 * N);
        CPA16(st + b_off1, b_g1 + (size_t)k0 * N);
        CPA_COMMIT();
    };

    float acc[2][8][4];
#pragma unroll
    for (int i = 0; i < 2; i++)
#pragma unroll
        for (int j = 0; j < 8; j++)
#pragma unroll
            for (int t = 0; t < 4; t++) acc[i][j][t] = 0.f;

    // per-lane ldmatrix offsets within a stage
    uint32_t a_rel[2], b_rel[4];
#pragma unroll
    for (int mi = 0; mi < 2; mi++)
        a_rel[mi] = (uint32_t)((wm * 32 + mi * 16 + (lane & 15)) * 80 + ((lane >> 4) * 8) * 2);
#pragma unroll
    for (int nc = 0; nc < 4; nc++)
        b_rel[nc] = (uint32_t)(10240 + (lane & 15) * 272 + (wn * 64 + nc * 16 + (lane >> 4) * 8) * 2);

    const int NK = Kp >> 5;   // 96
    issue(0); issue(1);
    for (int c = 0; c < NK; c++) {
        CPA_WAIT1();          // group c complete (uniform via dummy commits)
        __syncthreads();      // visibility + compute(c-1) done by all
        if (c + 2 < NK) issue(c + 2); else CPA_COMMIT();

        const uint32_t st = smem_u + (uint32_t)((c % 3) * STAGE_B);
#pragma unroll
        for (int kk = 0; kk < 2; kk++) {
            uint32_t af[2][4], bf[4][4];
#pragma unroll
            for (int mi = 0; mi < 2; mi++)
                LDMX4(af[mi][0], af[mi][1], af[mi][2], af[mi][3],
                      st + a_rel[mi] + kk * 32);
#pragma unroll
            for (int nc = 0; nc < 4; nc++)
                LDMX4T(bf[nc][0], bf[nc][1], bf[nc][2], bf[nc][3],
                       st + b_rel[nc] + kk * 16 * 272);
#pragma unroll
            for (int mi = 0; mi < 2; mi++)
#pragma unroll
                for (int nc = 0; nc < 4; nc++) {
                    MMA16816(acc[mi][nc * 2 + 0], af[mi], bf[nc][0], bf[nc][1]);
                    MMA16816(acc[mi][nc * 2 + 1], af[mi], bf[nc][2], bf[nc][3]);
                }
        }
    }
    __syncthreads();

    const int row_base = bm + wm * 32 + (lane >> 2);
    const int col_base = bn + wn * 64 + (lane & 3) * 2;

    if (EPI == 1) {
#pragma unroll
        for (int mi = 0; mi < 2; mi++) {
#pragma unroll
            for (int ni = 0; ni < 8; ni++) {
                const int c  = col_base + ni * 8;
                const int r0 = row_base + mi * 16;
                const float bx = bias[c], by = bias[c + 1];
                float2 v0 = make_float2(acc[mi][ni][0] + bx, acc[mi][ni][1] + by);
                float2 v1 = make_float2(acc[mi][ni][2] + bx, acc[mi][ni][3] + by);
                if (resid) {
                    float2 r0v = *(const float2*)(resid + (size_t)r0 * N + c);
                    float2 r1v = *(const float2*)(resid + (size_t)(r0 + 8) * N + c);
                    v0.x += r0v.x; v0.y += r0v.y;
                    v1.x += r1v.x; v1.y += r1v.y;
                }
                *(float2*)(C + (size_t)r0 * N + c)       = v0;
                *(float2*)(C + (size_t)(r0 + 8) * N + c) = v1;
            }
        }
    } else {
        // QKV: stage hi (pass 0) then lo (pass 1) through smem, stream coalesced
        __nv_bfloat16 (*St)[136] = (__nv_bfloat16(*)[136])smraw;
        const int lr0 = wm * 32 + (lane >> 2);
        const int lc0 = wn * 64 + ((lane & 3) << 1);
#pragma unroll
        for (int pass = 0; pass < 2; pass++) {
            if (pass) __syncthreads();
#pragma unroll
            for (int mi = 0; mi < 2; mi++) {
#pragma unroll
                for (int ni = 0; ni < 8; ni++) {
                    const int c = col_base + ni * 8;
                    const float bx = bias[c], by = bias[c + 1];
                    float v0x = acc[mi][ni][0] + bx, v0y = acc[mi][ni][1] + by;
                    float v1x = acc[mi][ni][2] + bx, v1y = acc[mi][ni][3] + by;
                    uint32_t w0, w1;
                    if (pass == 0) { w0 = pack_bf2(v0x, v0y); w1 = pack_bf2(v1x, v1y); }
                    else           { w0 = pack_lo2(v0x, v0y); w1 = pack_lo2(v1x, v1y); }
                    const int lc = lc0 + ni * 8;
                    *(uint32_t*)&St[lr0 + mi * 16][lc]     = w0;
                    *(uint32_t*)&St[lr0 + mi * 16 + 8][lc] = w1;
                }
            }
            __syncthreads();
            for (int i = tid; i < 2048; i += 256) {
                const int row = i >> 4, seg = i & 15;
                const int rg = bm + row;
                const int cg = bn + seg * 8;
                const int sec = cg >> 10;
                const int h   = (cg & 1023) >> 6;
                const int d   = cg & 63;
                __nv_bfloat16* base;
                if (pass == 0) base = (sec == 0) ? g_Qhi : (sec == 1) ? g_Khi : g_Vhi;
                else           base = (sec == 0) ? g_Qlo : (sec == 1) ? g_Klo : g_Vlo;
                size_t dst = (((size_t)((rg >> 11) * HH + h) * SS + (rg & 2047)) << 6) + d;
                *(uint4*)(base + dst) = *(uint4*)&St[row][seg * 8];
            }
        }
    }
}

// ---------------- tensor-core flash attention (round-12 verified) ----------------
#define ATTN_PAD 136
#define ROWB (ATTN_PAD*2)
#define Q_BYTES  (128*ROWB)
#define KV_TILE  (64*ROWB)
#define KV_PAIR  (2*KV_TILE)
#define MS_OFF   (Q_BYTES + 2*KV_PAIR)
#define ATTN_SMEM (MS_OFF + 2*128*8)

__global__ __launch_bounds__(256, 2)
void attn_mma()
{
    extern __shared__ char smc[];
    __nv_bfloat16 (*Qs)[ATTN_PAD] = (__nv_bfloat16(*)[ATTN_PAD])(smc);
    unsigned long long* Ms = (unsigned long long*)(smc + MS_OFF);
    const uint32_t smem_u = (uint32_t)__cvta_generic_to_shared(smc);

    const int tid  = threadIdx.x;
    const int lane = tid & 31;
    const int wid  = tid >> 5;
    const int wq   = wid << 4;
    const int b  = blockIdx.y >> 4;
    const int h  = blockIdx.y & 15;
    const int q0 = blockIdx.x << 7;
    const size_t head_base = ((size_t)(b * HH + h) * SS) << 6;

    for (int i = tid; i < 1024; i += 256) {
        int row = i >> 3, seg = (i & 7) << 3;
        size_t g = head_base + (size_t)(q0 + row) * 64 + seg;
        *(uint4*)&Qs[row][seg]      = *(const uint4*)(g_Qhi + g);
        *(uint4*)&Qs[row][64 + seg] = *(const uint4*)(g_Qlo + g);
    }

    const uint32_t a_base = (uint32_t)__cvta_generic_to_shared(
        &Qs[wq + (lane & 15)][(lane >> 4) * 8]);
    const int mat = lane >> 3, rr = lane & 7;
    const uint32_t k_lane = (uint32_t)((((mat >> 1) << 3) + rr) * ROWB + (mat & 1) * 16);
    const uint32_t v_lane = (uint32_t)((lane & 15) * ROWB + (lane >> 4) * 16);

    const int ld_row = tid >> 3, ld_seg = (tid & 7) << 3;
    const size_t mask_row_base = (size_t)(b * SS + q0 + tid) * SS;

    auto issue = [&](int k0, int buf) {
        const uint32_t kb = smem_u + Q_BYTES + buf * KV_PAIR;
        const uint32_t vb = kb + KV_TILE;
#pragma unroll
        for (int rep = 0; rep < 2; rep++) {
            const int row = ld_row + rep * 32;
            const size_t g = head_base + (size_t)(k0 + row) * 64 + ld_seg;
            const uint32_t so = row * ROWB + ld_seg * 2;
            CPA16(kb + so,       g_Khi + g);
            CPA16(kb + so + 128, g_Klo + g);
            CPA16(vb + so,       g_Vhi + g);
            CPA16(vb + so + 128, g_Vlo + g);
        }
        if (tid < 128) {
            const size_t wb = (mask_row_base + k0) >> 5;
            CPA8(smem_u + MS_OFF + buf * 1024 + tid * 8, (const char*)&g_maskbits[wb]);
        }
        CPA_COMMIT();
    };

    float oacc[8][4];
#pragma unroll
    for (int i = 0; i < 8; i++)
#pragma unroll
        for (int t = 0; t < 4; t++) oacc[i][t] = 0.f;
    float m0 = -INFINITY, m1 = -INFINITY, l0 = 0.f, l1 = 0.f;

    issue(0, 0);

    for (int t = 0; t < 32; t++) {
        const int buf = t & 1;
        if (t + 1 < 32) { issue((t + 1) << 6, buf ^ 1); CPA_WAIT1(); }
        else            { CPA_WAIT0(); }
        __syncthreads();

        const uint32_t kb_base = smem_u + Q_BYTES + buf * KV_PAIR + k_lane;
        const uint32_t vb_base = smem_u + Q_BYTES + buf * KV_PAIR + KV_TILE + v_lane;
        const unsigned long long* Mb = Ms + buf * 128;

        float sacc[8][4];
#pragma unroll
        for (int i = 0; i < 8; i++)
#pragma unroll
            for (int tt = 0; tt < 4; tt++) sacc[i][tt] = 0.f;

#pragma unroll
        for (int kk = 0; kk < 4; kk++) {
            uint32_t ah[4], al2[4];
            LDMX4(ah[0], ah[1], ah[2], ah[3], a_base + kk * 32);
            LDMX4(al2[0], al2[1], al2[2], al2[3], a_base + 128 + kk * 32);
#pragma unroll
            for (int g = 0; g < 4; g++) {
                uint32_t kh[4], kl[4];
                LDMX4(kh[0], kh[1], kh[2], kh[3], kb_base + g * (16 * ROWB) + kk * 32);
                MMA16816(sacc[2 * g + 0], ah, kh[0], kh[1]);
                MMA16816(sacc[2 * g + 1], ah, kh[2], kh[3]);
                MMA16816(sacc[2 * g + 0], al2, kh[0], kh[1]);
                MMA16816(sacc[2 * g + 1], al2, kh[2], kh[3]);
                LDMX4(kl[0], kl[1], kl[2], kl[3], kb_base + 128 + g * (16 * ROWB) + kk * 32);
                MMA16816(sacc[2 * g + 0], ah, kl[0], kl[1]);
                MMA16816(sacc[2 * g + 1], ah, kl[2], kl[3]);
            }
        }

        const int r0 = wq + (lane >> 2);
        const unsigned long long mw0 = Mb[r0];
        const unsigned long long mw1 = Mb[r0 + 8];
        const int cb0 = (lane & 3) << 1;
#pragma unroll
        for (int nb = 0; nb < 8; nb++) {
            int cb = (nb << 3) + cb0;
            sacc[nb][0] = ((mw0 >> cb) & 1ull)       ? -1e9f : sacc[nb][0] * 0.125f;
            sacc[nb][1] = ((mw0 >> (cb + 1)) & 1ull) ? -1e9f : sacc[nb][1] * 0.125f;
            sacc[nb][2] = ((mw1 >> cb) & 1ull)       ? -1e9f : sacc[nb][2] * 0.125f;
            sacc[nb][3] = ((mw1 >> (cb + 1)) & 1ull) ? -1e9f : sacc[nb][3] * 0.125f;
        }

        float mt0 = -1e30f, mt1 = -1e30f;
#pragma unroll
        for (int nb = 0; nb < 8; nb++) {
            mt0 = fmaxf(mt0, fmaxf(sacc[nb][0], sacc[nb][1]));
            mt1 = fmaxf(mt1, fmaxf(sacc[nb][2], sacc[nb][3]));
        }
        mt0 = fmaxf(mt0, __shfl_xor_sync(0xffffffffu, mt0, 1));
        mt0 = fmaxf(mt0, __shfl_xor_sync(0xffffffffu, mt0, 2));
        mt1 = fmaxf(mt1, __shfl_xor_sync(0xffffffffu, mt1, 1));
        mt1 = fmaxf(mt1, __shfl_xor_sync(0xffffffffu, mt1, 2));
        float mn0 = fmaxf(m0, mt0), mn1 = fmaxf(m1, mt1);
        float c0 = __expf(m0 - mn0), c1 = __expf(m1 - mn1);

        float ls0 = 0.f, ls1 = 0.f;
#pragma unroll
        for (int nb = 0; nb < 8; nb++) {
            sacc[nb][0] = __expf(sacc[nb][0] - mn0);
            sacc[nb][1] = __expf(sacc[nb][1] - mn0);
            sacc[nb][2] = __expf(sacc[nb][2] - mn1);
            sacc[nb][3] = __expf(sacc[nb][3] - mn1);
            ls0 += sacc[nb][0] + sacc[nb][1];
            ls1 += sacc[nb][2] + sacc[nb][3];
        }
        ls0 += __shfl_xor_sync(0xffffffffu, ls0, 1);
        ls0 += __shfl_xor_sync(0xffffffffu, ls0, 2);
        ls1 += __shfl_xor_sync(0xffffffffu, ls1, 1);
        ls1 += __shfl_xor_sync(0xffffffffu, ls1, 2);
        l0 = l0 * c0 + ls0; l1 = l1 * c1 + ls1;
        m0 = mn0; m1 = mn1;
#pragma unroll
        for (int nb = 0; nb < 8; nb++) {
            oacc[nb][0] *= c0; oacc[nb][1] *= c0;
            oacc[nb][2] *= c1; oacc[nb][3] *= c1;
        }

#pragma unroll
        for (int kk = 0; kk < 4; kk++) {
            uint32_t ph[4], pl[4];
            ph[0] = pack_bf2(sacc[2 * kk][0],     sacc[2 * kk][1]);
            ph[1] = pack_bf2(sacc[2 * kk][2],     sacc[2 * kk][3]);
            ph[2] = pack_bf2(sacc[2 * kk + 1][0], sacc[2 * kk + 1][1]);
            ph[3] = pack_bf2(sacc[2 * kk + 1][2], sacc[2 * kk + 1][3]);
            pl[0] = pack_lo2(sacc[2 * kk][0],     sacc[2 * kk][1]);
            pl[1] = pack_lo2(sacc[2 * kk][2],     sacc[2 * kk][3]);
            pl[2] = pack_lo2(sacc[2 * kk + 1][0], sacc[2 * kk + 1][1]);
            pl[3] = pack_lo2(sacc[2 * kk + 1][2], sacc[2 * kk + 1][3]);
#pragma unroll
            for (int nc = 0; nc < 4; nc++) {
                uint32_t vh[4], vl[4];
                LDMX4T(vh[0], vh[1], vh[2], vh[3], vb_base + nc * 32 + kk * (16 * ROWB));
                MMA16816(oacc[2 * nc + 0], ph, vh[0], vh[1]);
                MMA16816(oacc[2 * nc + 1], ph, vh[2], vh[3]);
                MMA16816(oacc[2 * nc + 0], pl, vh[0], vh[1]);
                MMA16816(oacc[2 * nc + 1], pl, vh[2], vh[3]);
                LDMX4T(vl[0], vl[1], vl[2], vl[3], vb_base + 128 + nc * 32 + kk * (16 * ROWB));
                MMA16816(oacc[2 * nc + 0], ph, vl[0], vl[1]);
                MMA16816(oacc[2 * nc + 1], ph, vl[2], vl[3]);
            }
        }
        __syncthreads();
    }

    {
        const float i0 = 1.0f / l0, i1 = 1.0f / l1;
        const int r0  = wq + (lane >> 2);
        const int cb0 = (lane & 3) << 1;
#pragma unroll
        for (int nb = 0; nb < 8; nb++) {
            int cb = (nb << 3) + cb0;
            float v0x = oacc[nb][0] * i0, v0y = oacc[nb][1] * i0;
            float v1x = oacc[nb][2] * i1, v1y = oacc[nb][3] * i1;
            *(uint32_t*)&Qs[r0][cb]          = pack_bf2(v0x, v0y);
            *(uint32_t*)&Qs[r0][64 + cb]     = pack_lo2(v0x, v0y);
            *(uint32_t*)&Qs[r0 + 8][cb]      = pack_bf2(v1x, v1y);
            *(uint32_t*)&Qs[r0 + 8][64 + cb] = pack_lo2(v1x, v1y);
        }
    }
    __syncthreads();
    for (int i = tid; i < 2048; i += 256) {
        const int row = i >> 4;
        const int seg = i & 15;
        __nv_bfloat16* dstrow = g_at3 + (size_t)(b * SS + q0 + row) * KP + h * 64;
        if (seg < 8) {
            uint4 v = *(uint4*)&Qs[row][seg * 8];
            *(uint4*)(dstrow + seg * 8)        = v;
            *(uint4*)(dstrow + 2048 + seg * 8) = v;
        } else {
            const int s = seg - 8;
            uint4 v = *(uint4*)&Qs[row][64 + s * 8];
            *(uint4*)(dstrow + 1024 + s * 8) = v;
        }
    }
}

// ---------------- LayerNorm ----------------
__global__ __launch_bounds__(256)
void ln_kernel(const float* __restrict__ y, const float* __restrict__ gam,
               const float* __restrict__ bet, float* __restrict__ out)
{
    const int row = blockIdx.x;
    const int tid = threadIdx.x;
    const float* yr = y + (size_t)row * 1024;
    float4 v = *(const float4*)(yr + (tid << 2));
    float s  = v.x + v.y + v.z + v.w;
    float ss = v.x * v.x + v.y * v.y + v.z * v.z + v.w * v.w;
#pragma unroll
    for (int off = 16; off; off >>= 1) {
        s  += __shfl_xor_sync(0xffffffffu, s,  off);
        ss += __shfl_xor_sync(0xffffffffu, ss, off);
    }
    __shared__ float red[16];
    __shared__ float stats[2];
    const int w = tid >> 5;
    if ((tid & 31) == 0) { red[w] = s; red[w + 8] = ss; }
    __syncthreads();
    if (tid == 0) {
        float ts = 0.f, tss = 0.f;
        for (int i = 0; i < 8; i++) { ts += red[i]; tss += red[i + 8]; }
        float mu  = ts * (1.0f / 1024.0f);
        float var = tss * (1.0f / 1024.0f) - mu * mu;
        stats[0] = mu;
        stats[1] = rsqrtf(var + 1e-5f);
    }
    __syncthreads();
    const float mu = stats[0], inv = stats[1];
    float4 g4 = *(const float4*)(gam + (tid << 2));
    float4 b4 = *(const float4*)(bet + (tid << 2));
    float4 rres;
    rres.x = (v.x - mu) * inv * g4.x + b4.x;
    rres.y = (v.y - mu) * inv * g4.y + b4.y;
    rres.z = (v.z - mu) * inv * g4.z + b4.z;
    rres.w = (v.w - mu) * inv * g4.w + b4.w;
    *(float4*)(out + (size_t)row * 1024 + (tid << 2)) = rres;
}

// ---------------- launch ----------------
extern "C" void kernel_launch(void* const* d_in, const int* in_sizes, int n_in,
                              void* d_out, int out_size)
{
    const float* x      = (const float*)d_in[0];
    const float* W_attn = (const float*)d_in[1];
    const float* b_attn = (const float*)d_in[2];
    const float* W_out  = (const float*)d_in[3];
    const float* b_out  = (const float*)d_in[4];
    const float* ln_g   = (const float*)d_in[5];
    const float* ln_b   = (const float*)d_in[6];
    const unsigned char* mask = (const unsigned char*)d_in[7];
    float* out = (float*)d_out;

    float* y;
    __nv_bfloat16 *x3, *at3, *wa3, *wo3;
    cudaGetSymbolAddress((void**)&y,    g_y);
    cudaGetSymbolAddress((void**)&x3,   g_x3);
    cudaGetSymbolAddress((void**)&at3,  g_at3);
    cudaGetSymbolAddress((void**)&wa3,  g_wa3);
    cudaGetSymbolAddress((void**)&wo3,  g_wo3);

    // 0) mask pack + operand conversions
    detect_mask_kernel<<<1, 1024>>>((const unsigned int*)mask);
    convert_mask_kernel<<<(BB * SS * SS) / 256, 256>>>(mask);
    cvt_A3<<<(MROWS * 1024) / 1024, 256>>>(x, x3, 1024);
    cvt_B3<<<(1024 * 3072) / 1024, 256>>>(W_attn, wa3, 1024, 3072);
    cvt_B3<<<(1024 * 1024) / 1024, 256>>>(W_out, wo3, 1024, 1024);

    // 1) QKV projection: epilogue writes per-head hi/lo split (smem-staged)
    dim3 g1(3072 / 128, MROWS / 128);
    gemm_bf16<0><<<g1, 256>>>(x3, wa3, b_attn, nullptr, nullptr, MROWS, 3072, KP);

    // 2) attention (tensor cores, cp.async double-buffered K/V)
    cudaFuncSetAttribute(attn_mma, cudaFuncAttributeMaxDynamicSharedMemorySize, ATTN_SMEM);
    dim3 g2(SS / 128, BB * HH);
    attn_mma<<<g2, 256, ATTN_SMEM>>>();

    // 3) out projection + residual
    dim3 g3(DD / 128, MROWS / 128);
    gemm_bf16<1><<<g3, 256>>>(at3, wo3, b_out, x, y, MROWS, DD, KP);

    // 4) LayerNorm
    ln_kernel<<<MROWS, 256>>>(y, ln_g, ln_b, out);
}

// round 15
// speedup vs baseline: 1.0461x; 1.0461x over previous
#include <cuda_runtime.h>
#include <cuda_bf16.h>
#include <math.h>
#include <stdint.h>

#define BB 2
#define SS 2048
#define DD 1024
#define HH 16
#define MROWS (BB*SS)   // 4096
#define KP 3072         // 3*K split depth

// ---------------- scratch (no cudaMalloc allowed) ----------------
__device__ float g_y[(size_t)MROWS * DD];
__device__ int   g_mask_mode;
__device__ __align__(8) unsigned int g_maskbits[(size_t)BB * SS * SS / 32];
__device__ __nv_bfloat16 g_x3[(size_t)MROWS * KP];
__device__ __nv_bfloat16 g_at3[(size_t)MROWS * KP];
__device__ __nv_bfloat16 g_wa3[(size_t)KP * 3072];
__device__ __nv_bfloat16 g_wo3[(size_t)KP * 1024];
#define HSZ ((size_t)BB * HH * SS * 64)
__device__ __nv_bfloat16 g_Qhi[HSZ], g_Qlo[HSZ];
__device__ __nv_bfloat16 g_Khi[HSZ], g_Klo[HSZ];
__device__ __nv_bfloat16 g_Vhi[HSZ], g_Vlo[HSZ];

// ---------------- mask dtype detection ----------------
__global__ void detect_mask_kernel(const unsigned int* __restrict__ m)
{
    __shared__ int sfloat, shigh;
    if (threadIdx.x == 0) { sfloat = 0; shigh = 0; }
    __syncthreads();
    int ff = 0, fh = 0;
    for (int i = threadIdx.x; i < 8192; i += blockDim.x) {
        unsigned int w = m[i];
        if (w == 0x3F800000u) ff = 1;
        else if (w & 0xFFFFFF00u) fh = 1;
    }
    if (ff) atomicOr(&sfloat, 1);
    if (fh) atomicOr(&shigh, 1);
    __syncthreads();
    if (threadIdx.x == 0)
        g_mask_mode = sfloat ? 2 : (shigh ? 1 : 0);
}

__global__ __launch_bounds__(256)
void convert_mask_kernel(const unsigned char* __restrict__ mb)
{
    const int mode = g_mask_mode;
    const int stride = (mode == 1) ? 1 : 4;
    const int offs   = (mode == 2) ? 3 : 0;
    size_t pos = (size_t)blockIdx.x * blockDim.x + threadIdx.x;
    unsigned char v = mb[pos * stride + offs];
    unsigned int bal = __ballot_sync(0xffffffffu, v != 0);
    if ((threadIdx.x & 31) == 0) g_maskbits[pos >> 5] = bal;
}

// ---------------- fp32 -> bf16x3 split conversions ----------------
__global__ __launch_bounds__(256)
void cvt_A3(const float* __restrict__ A, __nv_bfloat16* __restrict__ out, int K)
{
    size_t i = ((size_t)blockIdx.x * 256 + threadIdx.x) * 4;
    int m = (int)(i / K), k = (int)(i % K);
    float4 v = *(const float4*)(A + i);
    __nv_bfloat16 h[4], l[4];
    h[0] = __float2bfloat16_rn(v.x); l[0] = __float2bfloat16_rn(v.x - __bfloat162float(h[0]));
    h[1] = __float2bfloat16_rn(v.y); l[1] = __float2bfloat16_rn(v.y - __bfloat162float(h[1]));
    h[2] = __float2bfloat16_rn(v.z); l[2] = __float2bfloat16_rn(v.z - __bfloat162float(h[2]));
    h[3] = __float2bfloat16_rn(v.w); l[3] = __float2bfloat16_rn(v.w - __bfloat162float(h[3]));
    __nv_bfloat16* row = out + (size_t)m * (3 * K);
    *(uint2*)(row + k)         = *(uint2*)h;
    *(uint2*)(row + K + k)     = *(uint2*)l;
    *(uint2*)(row + 2 * K + k) = *(uint2*)h;
}

__global__ __launch_bounds__(256)
void cvt_B3(const float* __restrict__ B, __nv_bfloat16* __restrict__ out, int K, int N)
{
    size_t i = ((size_t)blockIdx.x * 256 + threadIdx.x) * 4;
    if (i >= (size_t)K * N) return;
    int r = (int)(i / N), c = (int)(i % N);
    float4 v = *(const float4*)(B + i);
    __nv_bfloat16 h[4], l[4];
    h[0] = __float2bfloat16_rn(v.x); l[0] = __float2bfloat16_rn(v.x - __bfloat162float(h[0]));
    h[1] = __float2bfloat16_rn(v.y); l[1] = __float2bfloat16_rn(v.y - __bfloat162float(h[1]));
    h[2] = __float2bfloat16_rn(v.z); l[2] = __float2bfloat16_rn(v.z - __bfloat162float(h[2]));
    h[3] = __float2bfloat16_rn(v.w); l[3] = __float2bfloat16_rn(v.w - __bfloat162float(h[3]));
    *(uint2*)(out + (size_t)r * N + c)           = *(uint2*)h;
    *(uint2*)(out + (size_t)(K + r) * N + c)     = *(uint2*)h;
    *(uint2*)(out + (size_t)(2 * K + r) * N + c) = *(uint2*)l;
}

// ---------------- MMA / cp.async macros ----------------
#define LDMX4(R0,R1,R2,R3,addr) \
    asm volatile("ldmatrix.sync.aligned.m8n8.x4.shared.b16 {%0,%1,%2,%3}, [%4];" \
        : "=r"(R0),"=r"(R1),"=r"(R2),"=r"(R3) : "r"(addr))
#define LDMX4T(R0,R1,R2,R3,addr) \
    asm volatile("ldmatrix.sync.aligned.m8n8.x4.trans.shared.b16 {%0,%1,%2,%3}, [%4];" \
        : "=r"(R0),"=r"(R1),"=r"(R2),"=r"(R3) : "r"(addr))
#define MMA16816(d, a, b0, b1) \
    asm volatile("mma.sync.aligned.m16n8k16.row.col.f32.bf16.bf16.f32 " \
        "{%0,%1,%2,%3}, {%4,%5,%6,%7}, {%8,%9}, {%0,%1,%2,%3};" \
        : "+f"(d[0]),"+f"(d[1]),"+f"(d[2]),"+f"(d[3]) \
        : "r"(a[0]),"r"(a[1]),"r"(a[2]),"r"(a[3]), "r"(b0),"r"(b1))
#define CPA16(saddr, gptr) \
    asm volatile("cp.async.cg.shared.global [%0], [%1], 16;" :: "r"(saddr), "l"(gptr))
#define CPA8(saddr, gptr) \
    asm volatile("cp.async.ca.shared.global [%0], [%1], 8;" :: "r"(saddr), "l"(gptr))
#define CPA_COMMIT() asm volatile("cp.async.commit_group;")
#define CPA_WAIT1()  asm volatile("cp.async.wait_group 1;")
#define CPA_WAIT0()  asm volatile("cp.async.wait_group 0;")

__device__ __forceinline__ uint32_t pack_bf2(float a, float b) {
    __nv_bfloat162 t = __floats2bfloat162_rn(a, b);
    return *(uint32_t*)&t;
}
__device__ __forceinline__ uint32_t pack_lo2(float a, float b) {
    float ha = __bfloat162float(__float2bfloat16_rn(a));
    float hb = __bfloat162float(__float2bfloat16_rn(b));
    return pack_bf2(a - ha, b - hb);
}

// ---------------- bf16 tensor-core GEMM, double-buffered smem ----------------
// EPI=0: epilogue stages per-head Q/K/V hi/lo split through smem (QKV proj)
// EPI=1: epilogue writes fp32 C with bias + residual (out proj)
#define A_OFF 0
#define B_OFF 20480
#define ABUF (128*40*2)
#define BBUF (32*136*2)
#define GEMM_SMEM 37888

template<int EPI>
__global__ __launch_bounds__(256)
void gemm_bf16(const __nv_bfloat16* __restrict__ A, const __nv_bfloat16* __restrict__ B,
               const float* __restrict__ bias, const float* __restrict__ resid,
               float* __restrict__ C, int M, int N, int Kp)
{
    __shared__ __align__(16) char smraw[GEMM_SMEM];
    __nv_bfloat16 (*As)[128][40]  = (__nv_bfloat16(*)[128][40])(smraw + A_OFF);
    __nv_bfloat16 (*Bs)[32][136]  = (__nv_bfloat16(*)[32][136])(smraw + B_OFF);

    const int tid  = threadIdx.x;
    const int lane = tid & 31;
    const int wid  = tid >> 5;
    const int wm   = wid & 3;
    const int wn   = wid >> 2;
    const int bm = blockIdx.y * 128, bn = blockIdx.x * 128;

    const int a_chunk = tid & 3;
    const int a_row   = tid >> 2;
    const int b_chunk = tid & 15;
    const int b_row   = tid >> 4;

    const __nv_bfloat16* Ag = A + (size_t)bm * Kp;
    const __nv_bfloat16* Bg = B + bn;

    uint4 ar0 = *(const uint4*)(Ag + (size_t)a_row * Kp + a_chunk * 8);
    uint4 ar1 = *(const uint4*)(Ag + (size_t)(a_row + 64) * Kp + a_chunk * 8);
    uint4 br0 = *(const uint4*)(Bg + (size_t)b_row * N + b_chunk * 8);
    uint4 br1 = *(const uint4*)(Bg + (size_t)(b_row + 16) * N + b_chunk * 8);
    *(uint4*)&As[0][a_row][a_chunk * 8]      = ar0;
    *(uint4*)&As[0][a_row + 64][a_chunk * 8] = ar1;
    *(uint4*)&Bs[0][b_row][b_chunk * 8]      = br0;
    *(uint4*)&Bs[0][b_row + 16][b_chunk * 8] = br1;
    __syncthreads();

    float acc[2][8][4];
#pragma unroll
    for (int i = 0; i < 2; i++)
#pragma unroll
        for (int j = 0; j < 8; j++)
#pragma unroll
            for (int t = 0; t < 4; t++) acc[i][j][t] = 0.f;

    uint32_t a_base[2], b_base[4];
#pragma unroll
    for (int mi = 0; mi < 2; mi++)
        a_base[mi] = (uint32_t)__cvta_generic_to_shared(
            &As[0][wm * 32 + mi * 16 + (lane & 15)][(lane >> 4) * 8]);
#pragma unroll
    for (int nc = 0; nc < 4; nc++)
        b_base[nc] = (uint32_t)__cvta_generic_to_shared(
            &Bs[0][lane & 15][wn * 64 + nc * 16 + (lane >> 4) * 8]);

    for (int k0 = 0; k0 < Kp; k0 += 32) {
        const int buf = (k0 >> 5) & 1;
        const uint32_t ao = buf * ABUF;
        const uint32_t bo = buf * BBUF;
        const bool more = (k0 + 32 < Kp);

        if (more) {
            const __nv_bfloat16* Ag2 = Ag + k0 + 32;
            const __nv_bfloat16* Bg2 = Bg + (size_t)(k0 + 32) * N;
            ar0 = *(const uint4*)(Ag2 + (size_t)a_row * Kp + a_chunk * 8);
            ar1 = *(const uint4*)(Ag2 + (size_t)(a_row + 64) * Kp + a_chunk * 8);
            br0 = *(const uint4*)(Bg2 + (size_t)b_row * N + b_chunk * 8);
            br1 = *(const uint4*)(Bg2 + (size_t)(b_row + 16) * N + b_chunk * 8);
        }

#pragma unroll
        for (int kk = 0; kk < 2; kk++) {
            uint32_t af[2][4], bf[4][4];
#pragma unroll
            for (int mi = 0; mi < 2; mi++)
                LDMX4(af[mi][0], af[mi][1], af[mi][2], af[mi][3],
                      a_base[mi] + ao + kk * 32);
#pragma unroll
            for (int nc = 0; nc < 4; nc++)
                LDMX4T(bf[nc][0], bf[nc][1], bf[nc][2], bf[nc][3],
                       b_base[nc] + bo + kk * 16 * 272);
#pragma unroll
            for (int mi = 0; mi < 2; mi++)
#pragma unroll
                for (int nc = 0; nc < 4; nc++) {
                    MMA16816(acc[mi][nc * 2 + 0], af[mi], bf[nc][0], bf[nc][1]);
                    MMA16816(acc[mi][nc * 2 + 1], af[mi], bf[nc][2], bf[nc][3]);
                }
        }

        if (more) {
            const int nb = buf ^ 1;
            *(uint4*)&As[nb][a_row][a_chunk * 8]      = ar0;
            *(uint4*)&As[nb][a_row + 64][a_chunk * 8] = ar1;
            *(uint4*)&Bs[nb][b_row][b_chunk * 8]      = br0;
            *(uint4*)&Bs[nb][b_row + 16][b_chunk * 8] = br1;
        }
        __syncthreads();
    }

    const int row_base = bm + wm * 32 + (lane >> 2);
    const int col_base = bn + wn * 64 + (lane & 3) * 2;

    if (EPI == 1) {
#pragma unroll
        for (int mi = 0; mi < 2; mi++) {
#pragma unroll
            for (int ni = 0; ni < 8; ni++) {
                const int c  = col_base + ni * 8;
                const int r0 = row_base + mi * 16;
                const float bx = bias[c], by = bias[c + 1];
                float2 v0 = make_float2(acc[mi][ni][0] + bx, acc[mi][ni][1] + by);
                float2 v1 = make_float2(acc[mi][ni][2] + bx, acc[mi][ni][3] + by);
                if (resid) {
                    float2 r0v = *(const float2*)(resid + (size_t)r0 * N + c);
                    float2 r1v = *(const float2*)(resid + (size_t)(r0 + 8) * N + c);
                    v0.x += r0v.x; v0.y += r0v.y;
                    v1.x += r1v.x; v1.y += r1v.y;
                }
                *(float2*)(C + (size_t)r0 * N + c)       = v0;
                *(float2*)(C + (size_t)(r0 + 8) * N + c) = v1;
            }
        }
    } else {
        // QKV: stage hi (pass 0) then lo (pass 1) through smem, stream coalesced
        __nv_bfloat16 (*St)[136] = (__nv_bfloat16(*)[136])smraw;
        const int lr0 = wm * 32 + (lane >> 2);
        const int lc0 = wn * 64 + ((lane & 3) << 1);
#pragma unroll
        for (int pass = 0; pass < 2; pass++) {
            if (pass) __syncthreads();
#pragma unroll
            for (int mi = 0; mi < 2; mi++) {
#pragma unroll
                for (int ni = 0; ni < 8; ni++) {
                    const int c = col_base + ni * 8;
                    const float bx = bias[c], by = bias[c + 1];
                    float v0x = acc[mi][ni][0] + bx, v0y = acc[mi][ni][1] + by;
                    float v1x = acc[mi][ni][2] + bx, v1y = acc[mi][ni][3] + by;
                    uint32_t w0, w1;
                    if (pass == 0) { w0 = pack_bf2(v0x, v0y); w1 = pack_bf2(v1x, v1y); }
                    else           { w0 = pack_lo2(v0x, v0y); w1 = pack_lo2(v1x, v1y); }
                    const int lc = lc0 + ni * 8;
                    *(uint32_t*)&St[lr0 + mi * 16][lc]     = w0;
                    *(uint32_t*)&St[lr0 + mi * 16 + 8][lc] = w1;
                }
            }
            __syncthreads();
            for (int i = tid; i < 2048; i += 256) {
                const int row = i >> 4, seg = i & 15;
                const int rg = bm + row;
                const int cg = bn + seg * 8;
                const int sec = cg >> 10;
                const int h   = (cg & 1023) >> 6;
                const int d   = cg & 63;
                __nv_bfloat16* base;
                if (pass == 0) base = (sec == 0) ? g_Qhi : (sec == 1) ? g_Khi : g_Vhi;
                else           base = (sec == 0) ? g_Qlo : (sec == 1) ? g_Klo : g_Vlo;
                size_t dst = (((size_t)((rg >> 11) * HH + h) * SS + (rg & 2047)) << 6) + d;
                *(uint4*)(base + dst) = *(uint4*)&St[row][seg * 8];
            }
        }
    }
}

// ---------------- tensor-core flash attention, 128-q tile, register-P ----------------
// K/V + mask double-buffered via cp.async; epilogue writes g_at3 split layout
// staged through smem.
#define ATTN_PAD 136
#define ROWB (ATTN_PAD*2)            // 272 bytes per row
#define Q_BYTES  (128*ROWB)          // 34816
#define KV_TILE  (64*ROWB)           // 17408
#define KV_PAIR  (2*KV_TILE)         // 34816
#define MS_OFF   (Q_BYTES + 2*KV_PAIR)   // 104448
#define ATTN_SMEM (MS_OFF + 2*128*8)     // 106496

__global__ __launch_bounds__(256, 2)
void attn_mma()
{
    extern __shared__ char smc[];
    __nv_bfloat16 (*Qs)[ATTN_PAD] = (__nv_bfloat16(*)[ATTN_PAD])(smc);
    unsigned long long* Ms = (unsigned long long*)(smc + MS_OFF);
    const uint32_t smem_u = (uint32_t)__cvta_generic_to_shared(smc);

    const int tid  = threadIdx.x;
    const int lane = tid & 31;
    const int wid  = tid >> 5;
    const int wq   = wid << 4;
    const int b  = blockIdx.y >> 4;
    const int h  = blockIdx.y & 15;
    const int q0 = blockIdx.x << 7;
    const size_t head_base = ((size_t)(b * HH + h) * SS) << 6;

    for (int i = tid; i < 1024; i += 256) {
        int row = i >> 3, seg = (i & 7) << 3;
        size_t g = head_base + (size_t)(q0 + row) * 64 + seg;
        *(uint4*)&Qs[row][seg]      = *(const uint4*)(g_Qhi + g);
        *(uint4*)&Qs[row][64 + seg] = *(const uint4*)(g_Qlo + g);
    }

    const uint32_t a_base = (uint32_t)__cvta_generic_to_shared(
        &Qs[wq + (lane & 15)][(lane >> 4) * 8]);
    const int mat = lane >> 3, rr = lane & 7;
    const uint32_t k_lane = (uint32_t)((((mat >> 1) << 3) + rr) * ROWB + (mat & 1) * 16);
    const uint32_t v_lane = (uint32_t)((lane & 15) * ROWB + (lane >> 4) * 16);

    const int ld_row = tid >> 3, ld_seg = (tid & 7) << 3;
    const size_t mask_row_base = (size_t)(b * SS + q0 + tid) * SS;

    auto issue = [&](int k0, int buf) {
        const uint32_t kb = smem_u + Q_BYTES + buf * KV_PAIR;
        const uint32_t vb = kb + KV_TILE;
#pragma unroll
        for (int rep = 0; rep < 2; rep++) {
            const int row = ld_row + rep * 32;
            const size_t g = head_base + (size_t)(k0 + row) * 64 + ld_seg;
            const uint32_t so = row * ROWB + ld_seg * 2;
            CPA16(kb + so,       g_Khi + g);
            CPA16(kb + so + 128, g_Klo + g);
            CPA16(vb + so,       g_Vhi + g);
            CPA16(vb + so + 128, g_Vlo + g);
        }
        if (tid < 128) {
            const size_t wb = (mask_row_base + k0) >> 5;
            CPA8(smem_u + MS_OFF + buf * 1024 + tid * 8, (const char*)&g_maskbits[wb]);
        }
        CPA_COMMIT();
    };

    float oacc[8][4];
#pragma unroll
    for (int i = 0; i < 8; i++)
#pragma unroll
        for (int t = 0; t < 4; t++) oacc[i][t] = 0.f;
    float m0 = -INFINITY, m1 = -INFINITY, l0 = 0.f, l1 = 0.f;

    issue(0, 0);

    for (int t = 0; t < 32; t++) {
        const int buf = t & 1;
        if (t + 1 < 32) { issue((t + 1) << 6, buf ^ 1); CPA_WAIT1(); }
        else            { CPA_WAIT0(); }
        __syncthreads();

        const uint32_t kb_base = smem_u + Q_BYTES + buf * KV_PAIR + k_lane;
        const uint32_t vb_base = smem_u + Q_BYTES + buf * KV_PAIR + KV_TILE + v_lane;
        const unsigned long long* Mb = Ms + buf * 128;

        float sacc[8][4];
#pragma unroll
        for (int i = 0; i < 8; i++)
#pragma unroll
            for (int tt = 0; tt < 4; tt++) sacc[i][tt] = 0.f;

#pragma unroll
        for (int kk = 0; kk < 4; kk++) {
            uint32_t ah[4], al2[4];
            LDMX4(ah[0], ah[1], ah[2], ah[3], a_base + kk * 32);
            LDMX4(al2[0], al2[1], al2[2], al2[3], a_base + 128 + kk * 32);
#pragma unroll
            for (int g = 0; g < 4; g++) {
                uint32_t kh[4], kl[4];
                LDMX4(kh[0], kh[1], kh[2], kh[3], kb_base + g * (16 * ROWB) + kk * 32);
                MMA16816(sacc[2 * g + 0], ah, kh[0], kh[1]);
                MMA16816(sacc[2 * g + 1], ah, kh[2], kh[3]);
                MMA16816(sacc[2 * g + 0], al2, kh[0], kh[1]);
                MMA16816(sacc[2 * g + 1], al2, kh[2], kh[3]);
                LDMX4(kl[0], kl[1], kl[2], kl[3], kb_base + 128 + g * (16 * ROWB) + kk * 32);
                MMA16816(sacc[2 * g + 0], ah, kl[0], kl[1]);
                MMA16816(sacc[2 * g + 1], ah, kl[2], kl[3]);
            }
        }

        const int r0 = wq + (lane >> 2);
        const unsigned long long mw0 = Mb[r0];
        const unsigned long long mw1 = Mb[r0 + 8];
        const int cb0 = (lane & 3) << 1;
#pragma unroll
        for (int nb = 0; nb < 8; nb++) {
            int cb = (nb << 3) + cb0;
            sacc[nb][0] = ((mw0 >> cb) & 1ull)       ? -1e9f : sacc[nb][0] * 0.125f;
            sacc[nb][1] = ((mw0 >> (cb + 1)) & 1ull) ? -1e9f : sacc[nb][1] * 0.125f;
            sacc[nb][2] = ((mw1 >> cb) & 1ull)       ? -1e9f : sacc[nb][2] * 0.125f;
            sacc[nb][3] = ((mw1 >> (cb + 1)) & 1ull) ? -1e9f : sacc[nb][3] * 0.125f;
        }

        float mt0 = -1e30f, mt1 = -1e30f;
#pragma unroll
        for (int nb = 0; nb < 8; nb++) {
            mt0 = fmaxf(mt0, fmaxf(sacc[nb][0], sacc[nb][1]));
            mt1 = fmaxf(mt1, fmaxf(sacc[nb][2], sacc[nb][3]));
        }
        mt0 = fmaxf(mt0, __shfl_xor_sync(0xffffffffu, mt0, 1));
        mt0 = fmaxf(mt0, __shfl_xor_sync(0xffffffffu, mt0, 2));
        mt1 = fmaxf(mt1, __shfl_xor_sync(0xffffffffu, mt1, 1));
        mt1 = fmaxf(mt1, __shfl_xor_sync(0xffffffffu, mt1, 2));
        float mn0 = fmaxf(m0, mt0), mn1 = fmaxf(m1, mt1);
        float c0 = __expf(m0 - mn0), c1 = __expf(m1 - mn1);

        float ls0 = 0.f, ls1 = 0.f;
#pragma unroll
        for (int nb = 0; nb < 8; nb++) {
            sacc[nb][0] = __expf(sacc[nb][0] - mn0);
            sacc[nb][1] = __expf(sacc[nb][1] - mn0);
            sacc[nb][2] = __expf(sacc[nb][2] - mn1);
            sacc[nb][3] = __expf(sacc[nb][3] - mn1);
            ls0 += sacc[nb][0] + sacc[nb][1];
            ls1 += sacc[nb][2] + sacc[nb][3];
        }
        ls0 += __shfl_xor_sync(0xffffffffu, ls0, 1);
        ls0 += __shfl_xor_sync(0xffffffffu, ls0, 2);
        ls1 += __shfl_xor_sync(0xffffffffu, ls1, 1);
        ls1 += __shfl_xor_sync(0xffffffffu, ls1, 2);
        l0 = l0 * c0 + ls0; l1 = l1 * c1 + ls1;
        m0 = mn0; m1 = mn1;
#pragma unroll
        for (int nb = 0; nb < 8; nb++) {
            oacc[nb][0] *= c0; oacc[nb][1] *= c0;
            oacc[nb][2] *= c1; oacc[nb][3] *= c1;
        }

#pragma unroll
        for (int kk = 0; kk < 4; kk++) {
            uint32_t ph[4], pl[4];
            ph[0] = pack_bf2(sacc[2 * kk][0],     sacc[2 * kk][1]);
            ph[1] = pack_bf2(sacc[2 * kk][2],     sacc[2 * kk][3]);
            ph[2] = pack_bf2(sacc[2 * kk + 1][0], sacc[2 * kk + 1][1]);
            ph[3] = pack_bf2(sacc[2 * kk + 1][2], sacc[2 * kk + 1][3]);
            pl[0] = pack_lo2(sacc[2 * kk][0],     sacc[2 * kk][1]);
            pl[1] = pack_lo2(sacc[2 * kk][2],     sacc[2 * kk][3]);
            pl[2] = pack_lo2(sacc[2 * kk + 1][0], sacc[2 * kk + 1][1]);
            pl[3] = pack_lo2(sacc[2 * kk + 1][2], sacc[2 * kk + 1][3]);
#pragma unroll
            for (int nc = 0; nc < 4; nc++) {
                uint32_t vh[4], vl[4];
                LDMX4T(vh[0], vh[1], vh[2], vh[3], vb_base + nc * 32 + kk * (16 * ROWB));
                MMA16816(oacc[2 * nc + 0], ph, vh[0], vh[1]);
                MMA16816(oacc[2 * nc + 1], ph, vh[2], vh[3]);
                MMA16816(oacc[2 * nc + 0], pl, vh[0], vh[1]);
                MMA16816(oacc[2 * nc + 1], pl, vh[2], vh[3]);
                LDMX4T(vl[0], vl[1], vl[2], vl[3], vb_base + 128 + nc * 32 + kk * (16 * ROWB));
                MMA16816(oacc[2 * nc + 0], ph, vl[0], vl[1]);
                MMA16816(oacc[2 * nc + 1], ph, vl[2], vl[3]);
            }
        }
        __syncthreads();
    }

    {
        const float i0 = 1.0f / l0, i1 = 1.0f / l1;
        const int r0  = wq + (lane >> 2);
        const int cb0 = (lane & 3) << 1;
#pragma unroll
        for (int nb = 0; nb < 8; nb++) {
            int cb = (nb << 3) + cb0;
            float v0x = oacc[nb][0] * i0, v0y = oacc[nb][1] * i0;
            float v1x = oacc[nb][2] * i1, v1y = oacc[nb][3] * i1;
            *(uint32_t*)&Qs[r0][cb]          = pack_bf2(v0x, v0y);
            *(uint32_t*)&Qs[r0][64 + cb]     = pack_lo2(v0x, v0y);
            *(uint32_t*)&Qs[r0 + 8][cb]      = pack_bf2(v1x, v1y);
            *(uint32_t*)&Qs[r0 + 8][64 + cb] = pack_lo2(v1x, v1y);
        }
    }
    __syncthreads();
    for (int i = tid; i < 2048; i += 256) {
        const int row = i >> 4;
        const int seg = i & 15;
        __nv_bfloat16* dstrow = g_at3 + (size_t)(b * SS + q0 + row) * KP + h * 64;
        if (seg < 8) {
            uint4 v = *(uint4*)&Qs[row][seg * 8];
            *(uint4*)(dstrow + seg * 8)        = v;
            *(uint4*)(dstrow + 2048 + seg * 8) = v;
        } else {
            const int s = seg - 8;
            uint4 v = *(uint4*)&Qs[row][64 + s * 8];
            *(uint4*)(dstrow + 1024 + s * 8) = v;
        }
    }
}

// ---------------- LayerNorm ----------------
__global__ __launch_bounds__(256)
void ln_kernel(const float* __restrict__ y, const float* __restrict__ gam,
               const float* __restrict__ bet, float* __restrict__ out)
{
    const int row = blockIdx.x;
    const int tid = threadIdx.x;
    const float* yr = y + (size_t)row * 1024;
    float4 v = *(const float4*)(yr + (tid << 2));
    float s  = v.x + v.y + v.z + v.w;
    float ss = v.x * v.x + v.y * v.y + v.z * v.z + v.w * v.w;
#pragma unroll
    for (int off = 16; off; off >>= 1) {
        s  += __shfl_xor_sync(0xffffffffu, s,  off);
        ss += __shfl_xor_sync(0xffffffffu, ss, off);
    }
    __shared__ float red[16];
    __shared__ float stats[2];
    const int w = tid >> 5;
    if ((tid & 31) == 0) { red[w] = s; red[w + 8] = ss; }
    __syncthreads();
    if (tid == 0) {
        float ts = 0.f, tss = 0.f;
        for (int i = 0; i < 8; i++) { ts += red[i]; tss += red[i + 8]; }
        float mu  = ts * (1.0f / 1024.0f);
        float var = tss * (1.0f / 1024.0f) - mu * mu;
        stats[0] = mu;
        stats[1] = rsqrtf(var + 1e-5f);
    }
    __syncthreads();
    const float mu = stats[0], inv = stats[1];
    float4 g4 = *(const float4*)(gam + (tid << 2));
    float4 b4 = *(const float4*)(bet + (tid << 2));
    float4 rres;
    rres.x = (v.x - mu) * inv * g4.x + b4.x;
    rres.y = (v.y - mu) * inv * g4.y + b4.y;
    rres.z = (v.z - mu) * inv * g4.z + b4.z;
    rres.w = (v.w - mu) * inv * g4.w + b4.w;
    *(float4*)(out + (size_t)row * 1024 + (tid << 2)) = rres;
}

// ---------------- launch ----------------
extern "C" void kernel_launch(void* const* d_in, const int* in_sizes, int n_in,
                              void* d_out, int out_size)
{
    const float* x      = (const float*)d_in[0];
    const float* W_attn = (const float*)d_in[1];
    const float* b_attn = (const float*)d_in[2];
    const float* W_out  = (const float*)d_in[3];
    const float* b_out  = (const float*)d_in[4];
    const float* ln_g   = (const float*)d_in[5];
    const float* ln_b   = (const float*)d_in[6];
    const unsigned char* mask = (const unsigned char*)d_in[7];
    float* out = (float*)d_out;

    float* y;
    __nv_bfloat16 *x3, *at3, *wa3, *wo3;
    cudaGetSymbolAddress((void**)&y,    g_y);
    cudaGetSymbolAddress((void**)&x3,   g_x3);
    cudaGetSymbolAddress((void**)&at3,  g_at3);
    cudaGetSymbolAddress((void**)&wa3,  g_wa3);
    cudaGetSymbolAddress((void**)&wo3,  g_wo3);

    // 0) mask pack + operand conversions
    detect_mask_kernel<<<1, 1024>>>((const unsigned int*)mask);
    convert_mask_kernel<<<(BB * SS * SS) / 256, 256>>>(mask);
    cvt_A3<<<(MROWS * 1024) / 1024, 256>>>(x, x3, 1024);
    cvt_B3<<<(1024 * 3072) / 1024, 256>>>(W_attn, wa3, 1024, 3072);
    cvt_B3<<<(1024 * 1024) / 1024, 256>>>(W_out, wo3, 1024, 1024);

    // 1) QKV projection: epilogue writes per-head hi/lo split (smem-staged)
    dim3 g1(3072 / 128, MROWS / 128);
    gemm_bf16<0><<<g1, 256>>>(x3, wa3, b_attn, nullptr, nullptr, MROWS, 3072, KP);

    // 2) attention (tensor cores, cp.async double-buffered K/V)
    cudaFuncSetAttribute(attn_mma, cudaFuncAttributeMaxDynamicSharedMemorySize, ATTN_SMEM);
    dim3 g2(SS / 128, BB * HH);
    attn_mma<<<g2, 256, ATTN_SMEM>>>();

    // 3) out projection + residual
    dim3 g3(DD / 128, MROWS / 128);
    gemm_bf16<1><<<g3, 256>>>(at3, wo3, b_out, x, y, MROWS, DD, KP);

    // 4) LayerNorm
    ln_kernel<<<MROWS, 256>>>(y, ln_g, ln_b, out);
}

// round 16
// speedup vs baseline: 1.0656x; 1.0186x over previous
#include <cuda_runtime.h>
#include <cuda_bf16.h>
#include <math.h>
#include <stdint.h>

#define BB 2
#define SS 2048
#define DD 1024
#define HH 16
#define MROWS (BB*SS)   // 4096
#define KP 3072         // 3*K split depth

// ---------------- scratch (no cudaMalloc allowed) ----------------
__device__ float g_y[(size_t)MROWS * DD];
__device__ int   g_mask_mode;
__device__ __align__(8) unsigned int g_maskbits[(size_t)BB * SS * SS / 32];
__device__ __nv_bfloat16 g_x3[(size_t)MROWS * KP];
__device__ __nv_bfloat16 g_at3[(size_t)MROWS * KP];
__device__ __nv_bfloat16 g_wa3[(size_t)KP * 3072];
__device__ __nv_bfloat16 g_wo3[(size_t)KP * 1024];
#define HSZ ((size_t)BB * HH * SS * 64)
__device__ __nv_bfloat16 g_Qhi[HSZ], g_Qlo[HSZ];
__device__ __nv_bfloat16 g_Khi[HSZ], g_Klo[HSZ];
__device__ __nv_bfloat16 g_Vhi[HSZ], g_Vlo[HSZ];

// ---------------- mask dtype detection ----------------
// word mode (0/2): elements are 4-byte (int32 or float32) -> nonzero-word test
// byte mode (1): elements are 1-byte bools
__global__ void detect_mask_kernel(const unsigned int* __restrict__ m)
{
    __shared__ int sfloat, shigh;
    if (threadIdx.x == 0) { sfloat = 0; shigh = 0; }
    __syncthreads();
    int ff = 0, fh = 0;
    for (int i = threadIdx.x; i < 8192; i += blockDim.x) {
        unsigned int w = m[i];
        if (w == 0x3F800000u) ff = 1;
        else if (w & 0xFFFFFF00u) fh = 1;
    }
    if (ff) atomicOr(&sfloat, 1);
    if (fh) atomicOr(&shigh, 1);
    __syncthreads();
    if (threadIdx.x == 0)
        g_mask_mode = sfloat ? 2 : (shigh ? 1 : 0);
}

// one thread -> one 32-bit mask word (32 positions), fully vectorized loads
__global__ __launch_bounds__(256)
void convert_mask_kernel(const unsigned char* __restrict__ mb)
{
    const int mode = g_mask_mode;
    const size_t w = (size_t)blockIdx.x * 256 + threadIdx.x;
    unsigned int bits = 0;
    if (mode == 1) {
        // byte bools: 32 bytes = 2 x uint4
        const uint4* p = (const uint4*)(mb + (w << 5));
        uint4 a = p[0], b = p[1];
        unsigned int arr[8] = {a.x, a.y, a.z, a.w, b.x, b.y, b.z, b.w};
#pragma unroll
        for (int i = 0; i < 8; i++) {
            unsigned int v = arr[i];
            bits |= ((v & 0x000000FFu) ? 1u : 0u) << (4 * i + 0);
            bits |= ((v & 0x0000FF00u) ? 1u : 0u) << (4 * i + 1);
            bits |= ((v & 0x00FF0000u) ? 1u : 0u) << (4 * i + 2);
            bits |= ((v & 0xFF000000u) ? 1u : 0u) << (4 * i + 3);
        }
    } else {
        // word bools (int32 or float32): 32 words = 8 x uint4, nonzero = true
        const uint4* p = (const uint4*)mb + (w << 3);
#pragma unroll
        for (int i = 0; i < 8; i++) {
            uint4 v = p[i];
            const int base = i * 4;
            bits |= (v.x ? 1u : 0u) << (base + 0);
            bits |= (v.y ? 1u : 0u) << (base + 1);
            bits |= (v.z ? 1u : 0u) << (base + 2);
            bits |= (v.w ? 1u : 0u) << (base + 3);
        }
    }
    g_maskbits[w] = bits;
}

// ---------------- fp32 -> bf16x3 split conversions ----------------
__global__ __launch_bounds__(256)
void cvt_A3(const float* __restrict__ A, __nv_bfloat16* __restrict__ out, int K)
{
    size_t i = ((size_t)blockIdx.x * 256 + threadIdx.x) * 4;
    int m = (int)(i / K), k = (int)(i % K);
    float4 v = *(const float4*)(A + i);
    __nv_bfloat16 h[4], l[4];
    h[0] = __float2bfloat16_rn(v.x); l[0] = __float2bfloat16_rn(v.x - __bfloat162float(h[0]));
    h[1] = __float2bfloat16_rn(v.y); l[1] = __float2bfloat16_rn(v.y - __bfloat162float(h[1]));
    h[2] = __float2bfloat16_rn(v.z); l[2] = __float2bfloat16_rn(v.z - __bfloat162float(h[2]));
    h[3] = __float2bfloat16_rn(v.w); l[3] = __float2bfloat16_rn(v.w - __bfloat162float(h[3]));
    __nv_bfloat16* row = out + (size_t)m * (3 * K);
    *(uint2*)(row + k)         = *(uint2*)h;
    *(uint2*)(row + K + k)     = *(uint2*)l;
    *(uint2*)(row + 2 * K + k) = *(uint2*)h;
}

__global__ __launch_bounds__(256)
void cvt_B3(const float* __restrict__ B, __nv_bfloat16* __restrict__ out, int K, int N)
{
    size_t i = ((size_t)blockIdx.x * 256 + threadIdx.x) * 4;
    if (i >= (size_t)K * N) return;
    int r = (int)(i / N), c = (int)(i % N);
    float4 v = *(const float4*)(B + i);
    __nv_bfloat16 h[4], l[4];
    h[0] = __float2bfloat16_rn(v.x); l[0] = __float2bfloat16_rn(v.x - __bfloat162float(h[0]));
    h[1] = __float2bfloat16_rn(v.y); l[1] = __float2bfloat16_rn(v.y - __bfloat162float(h[1]));
    h[2] = __float2bfloat16_rn(v.z); l[2] = __float2bfloat16_rn(v.z - __bfloat162float(h[2]));
    h[3] = __float2bfloat16_rn(v.w); l[3] = __float2bfloat16_rn(v.w - __bfloat162float(h[3]));
    *(uint2*)(out + (size_t)r * N + c)           = *(uint2*)h;
    *(uint2*)(out + (size_t)(K + r) * N + c)     = *(uint2*)h;
    *(uint2*)(out + (size_t)(2 * K + r) * N + c) = *(uint2*)l;
}

// ---------------- MMA / cp.async macros ----------------
#define LDMX4(R0,R1,R2,R3,addr) \
    asm volatile("ldmatrix.sync.aligned.m8n8.x4.shared.b16 {%0,%1,%2,%3}, [%4];" \
        : "=r"(R0),"=r"(R1),"=r"(R2),"=r"(R3) : "r"(addr))
#define LDMX4T(R0,R1,R2,R3,addr) \
    asm volatile("ldmatrix.sync.aligned.m8n8.x4.trans.shared.b16 {%0,%1,%2,%3}, [%4];" \
        : "=r"(R0),"=r"(R1),"=r"(R2),"=r"(R3) : "r"(addr))
#define MMA16816(d, a, b0, b1) \
    asm volatile("mma.sync.aligned.m16n8k16.row.col.f32.bf16.bf16.f32 " \
        "{%0,%1,%2,%3}, {%4,%5,%6,%7}, {%8,%9}, {%0,%1,%2,%3};" \
        : "+f"(d[0]),"+f"(d[1]),"+f"(d[2]),"+f"(d[3]) \
        : "r"(a[0]),"r"(a[1]),"r"(a[2]),"r"(a[3]), "r"(b0),"r"(b1))
#define CPA16(saddr, gptr) \
    asm volatile("cp.async.cg.shared.global [%0], [%1], 16;" :: "r"(saddr), "l"(gptr))
#define CPA8(saddr, gptr) \
    asm volatile("cp.async.ca.shared.global [%0], [%1], 8;" :: "r"(saddr), "l"(gptr))
#define CPA_COMMIT() asm volatile("cp.async.commit_group;")
#define CPA_WAIT1()  asm volatile("cp.async.wait_group 1;")
#define CPA_WAIT0()  asm volatile("cp.async.wait_group 0;")

__device__ __forceinline__ uint32_t pack_bf2(float a, float b) {
    __nv_bfloat162 t = __floats2bfloat162_rn(a, b);
    return *(uint32_t*)&t;
}
__device__ __forceinline__ uint32_t pack_lo2(float a, float b) {
    float ha = __bfloat162float(__float2bfloat16_rn(a));
    float hb = __bfloat162float(__float2bfloat16_rn(b));
    return pack_bf2(a - ha, b - hb);
}

// ---------------- bf16 tensor-core GEMM, double-buffered smem ----------------
// EPI=0: epilogue stages per-head Q/K/V hi/lo split through smem (QKV proj)
// EPI=1: epilogue writes fp32 C with bias + residual (out proj)
#define A_OFF 0
#define B_OFF 20480
#define ABUF (128*40*2)
#define BBUF (32*136*2)
#define GEMM_SMEM 37888

template<int EPI>
__global__ __launch_bounds__(256)
void gemm_bf16(const __nv_bfloat16* __restrict__ A, const __nv_bfloat16* __restrict__ B,
               const float* __restrict__ bias, const float* __restrict__ resid,
               float* __restrict__ C, int M, int N, int Kp)
{
    __shared__ __align__(16) char smraw[GEMM_SMEM];
    __nv_bfloat16 (*As)[128][40]  = (__nv_bfloat16(*)[128][40])(smraw + A_OFF);
    __nv_bfloat16 (*Bs)[32][136]  = (__nv_bfloat16(*)[32][136])(smraw + B_OFF);

    const int tid  = threadIdx.x;
    const int lane = tid & 31;
    const int wid  = tid >> 5;
    const int wm   = wid & 3;
    const int wn   = wid >> 2;
    const int bm = blockIdx.y * 128, bn = blockIdx.x * 128;

    const int a_chunk = tid & 3;
    const int a_row   = tid >> 2;
    const int b_chunk = tid & 15;
    const int b_row   = tid >> 4;

    const __nv_bfloat16* Ag = A + (size_t)bm * Kp;
    const __nv_bfloat16* Bg = B + bn;

    uint4 ar0 = *(const uint4*)(Ag + (size_t)a_row * Kp + a_chunk * 8);
    uint4 ar1 = *(const uint4*)(Ag + (size_t)(a_row + 64) * Kp + a_chunk * 8);
    uint4 br0 = *(const uint4*)(Bg + (size_t)b_row * N + b_chunk * 8);
    uint4 br1 = *(const uint4*)(Bg + (size_t)(b_row + 16) * N + b_chunk * 8);
    *(uint4*)&As[0][a_row][a_chunk * 8]      = ar0;
    *(uint4*)&As[0][a_row + 64][a_chunk * 8] = ar1;
    *(uint4*)&Bs[0][b_row][b_chunk * 8]      = br0;
    *(uint4*)&Bs[0][b_row + 16][b_chunk * 8] = br1;
    __syncthreads();

    float acc[2][8][4];
#pragma unroll
    for (int i = 0; i < 2; i++)
#pragma unroll
        for (int j = 0; j < 8; j++)
#pragma unroll
            for (int t = 0; t < 4; t++) acc[i][j][t] = 0.f;

    uint32_t a_base[2], b_base[4];
#pragma unroll
    for (int mi = 0; mi < 2; mi++)
        a_base[mi] = (uint32_t)__cvta_generic_to_shared(
            &As[0][wm * 32 + mi * 16 + (lane & 15)][(lane >> 4) * 8]);
#pragma unroll
    for (int nc = 0; nc < 4; nc++)
        b_base[nc] = (uint32_t)__cvta_generic_to_shared(
            &Bs[0][lane & 15][wn * 64 + nc * 16 + (lane >> 4) * 8]);

    for (int k0 = 0; k0 < Kp; k0 += 32) {
        const int buf = (k0 >> 5) & 1;
        const uint32_t ao = buf * ABUF;
        const uint32_t bo = buf * BBUF;
        const bool more = (k0 + 32 < Kp);

        if (more) {
            const __nv_bfloat16* Ag2 = Ag + k0 + 32;
            const __nv_bfloat16* Bg2 = Bg + (size_t)(k0 + 32) * N;
            ar0 = *(const uint4*)(Ag2 + (size_t)a_row * Kp + a_chunk * 8);
            ar1 = *(const uint4*)(Ag2 + (size_t)(a_row + 64) * Kp + a_chunk * 8);
            br0 = *(const uint4*)(Bg2 + (size_t)b_row * N + b_chunk * 8);
            br1 = *(const uint4*)(Bg2 + (size_t)(b_row + 16) * N + b_chunk * 8);
        }

#pragma unroll
        for (int kk = 0; kk < 2; kk++) {
            uint32_t af[2][4], bf[4][4];
#pragma unroll
            for (int mi = 0; mi < 2; mi++)
                LDMX4(af[mi][0], af[mi][1], af[mi][2], af[mi][3],
                      a_base[mi] + ao + kk * 32);
#pragma unroll
            for (int nc = 0; nc < 4; nc++)
                LDMX4T(bf[nc][0], bf[nc][1], bf[nc][2], bf[nc][3],
                       b_base[nc] + bo + kk * 16 * 272);
#pragma unroll
            for (int mi = 0; mi < 2; mi++)
#pragma unroll
                for (int nc = 0; nc < 4; nc++) {
                    MMA16816(acc[mi][nc * 2 + 0], af[mi], bf[nc][0], bf[nc][1]);
                    MMA16816(acc[mi][nc * 2 + 1], af[mi], bf[nc][2], bf[nc][3]);
                }
        }

        if (more) {
            const int nb = buf ^ 1;
            *(uint4*)&As[nb][a_row][a_chunk * 8]      = ar0;
            *(uint4*)&As[nb][a_row + 64][a_chunk * 8] = ar1;
            *(uint4*)&Bs[nb][b_row][b_chunk * 8]      = br0;
            *(uint4*)&Bs[nb][b_row + 16][b_chunk * 8] = br1;
        }
        __syncthreads();
    }

    const int row_base = bm + wm * 32 + (lane >> 2);
    const int col_base = bn + wn * 64 + (lane & 3) * 2;

    if (EPI == 1) {
#pragma unroll
        for (int mi = 0; mi < 2; mi++) {
#pragma unroll
            for (int ni = 0; ni < 8; ni++) {
                const int c  = col_base + ni * 8;
                const int r0 = row_base + mi * 16;
                const float bx = bias[c], by = bias[c + 1];
                float2 v0 = make_float2(acc[mi][ni][0] + bx, acc[mi][ni][1] + by);
                float2 v1 = make_float2(acc[mi][ni][2] + bx, acc[mi][ni][3] + by);
                if (resid) {
                    float2 r0v = *(const float2*)(resid + (size_t)r0 * N + c);
                    float2 r1v = *(const float2*)(resid + (size_t)(r0 + 8) * N + c);
                    v0.x += r0v.x; v0.y += r0v.y;
                    v1.x += r1v.x; v1.y += r1v.y;
                }
                *(float2*)(C + (size_t)r0 * N + c)       = v0;
                *(float2*)(C + (size_t)(r0 + 8) * N + c) = v1;
            }
        }
    } else {
        // QKV: stage hi (pass 0) then lo (pass 1) through smem, stream coalesced
        __nv_bfloat16 (*St)[136] = (__nv_bfloat16(*)[136])smraw;
        const int lr0 = wm * 32 + (lane >> 2);
        const int lc0 = wn * 64 + ((lane & 3) << 1);
#pragma unroll
        for (int pass = 0; pass < 2; pass++) {
            if (pass) __syncthreads();
#pragma unroll
            for (int mi = 0; mi < 2; mi++) {
#pragma unroll
                for (int ni = 0; ni < 8; ni++) {
                    const int c = col_base + ni * 8;
                    const float bx = bias[c], by = bias[c + 1];
                    float v0x = acc[mi][ni][0] + bx, v0y = acc[mi][ni][1] + by;
                    float v1x = acc[mi][ni][2] + bx, v1y = acc[mi][ni][3] + by;
                    uint32_t w0, w1;
                    if (pass == 0) { w0 = pack_bf2(v0x, v0y); w1 = pack_bf2(v1x, v1y); }
                    else           { w0 = pack_lo2(v0x, v0y); w1 = pack_lo2(v1x, v1y); }
                    const int lc = lc0 + ni * 8;
                    *(uint32_t*)&St[lr0 + mi * 16][lc]     = w0;
                    *(uint32_t*)&St[lr0 + mi * 16 + 8][lc] = w1;
                }
            }
            __syncthreads();
            for (int i = tid; i < 2048; i += 256) {
                const int row = i >> 4, seg = i & 15;
                const int rg = bm + row;
                const int cg = bn + seg * 8;
                const int sec = cg >> 10;
                const int h   = (cg & 1023) >> 6;
                const int d   = cg & 63;
                __nv_bfloat16* base;
                if (pass == 0) base = (sec == 0) ? g_Qhi : (sec == 1) ? g_Khi : g_Vhi;
                else           base = (sec == 0) ? g_Qlo : (sec == 1) ? g_Klo : g_Vlo;
                size_t dst = (((size_t)((rg >> 11) * HH + h) * SS + (rg & 2047)) << 6) + d;
                *(uint4*)(base + dst) = *(uint4*)&St[row][seg * 8];
            }
        }
    }
}

// ---------------- tensor-core flash attention, 128-q tile, register-P ----------------
// K/V + mask double-buffered via cp.async; epilogue writes g_at3 split layout
// staged through smem.
#define ATTN_PAD 136
#define ROWB (ATTN_PAD*2)            // 272 bytes per row
#define Q_BYTES  (128*ROWB)          // 34816
#define KV_TILE  (64*ROWB)           // 17408
#define KV_PAIR  (2*KV_TILE)         // 34816
#define MS_OFF   (Q_BYTES + 2*KV_PAIR)   // 104448
#define ATTN_SMEM (MS_OFF + 2*128*8)     // 106496

__global__ __launch_bounds__(256, 2)
void attn_mma()
{
    extern __shared__ char smc[];
    __nv_bfloat16 (*Qs)[ATTN_PAD] = (__nv_bfloat16(*)[ATTN_PAD])(smc);
    unsigned long long* Ms = (unsigned long long*)(smc + MS_OFF);
    const uint32_t smem_u = (uint32_t)__cvta_generic_to_shared(smc);

    const int tid  = threadIdx.x;
    const int lane = tid & 31;
    const int wid  = tid >> 5;
    const int wq   = wid << 4;
    const int b  = blockIdx.y >> 4;
    const int h  = blockIdx.y & 15;
    const int q0 = blockIdx.x << 7;
    const size_t head_base = ((size_t)(b * HH + h) * SS) << 6;

    for (int i = tid; i < 1024; i += 256) {
        int row = i >> 3, seg = (i & 7) << 3;
        size_t g = head_base + (size_t)(q0 + row) * 64 + seg;
        *(uint4*)&Qs[row][seg]      = *(const uint4*)(g_Qhi + g);
        *(uint4*)&Qs[row][64 + seg] = *(const uint4*)(g_Qlo + g);
    }

    const uint32_t a_base = (uint32_t)__cvta_generic_to_shared(
        &Qs[wq + (lane & 15)][(lane >> 4) * 8]);
    const int mat = lane >> 3, rr = lane & 7;
    const uint32_t k_lane = (uint32_t)((((mat >> 1) << 3) + rr) * ROWB + (mat & 1) * 16);
    const uint32_t v_lane = (uint32_t)((lane & 15) * ROWB + (lane >> 4) * 16);

    const int ld_row = tid >> 3, ld_seg = (tid & 7) << 3;
    const size_t mask_row_base = (size_t)(b * SS + q0 + tid) * SS;

    auto issue = [&](int k0, int buf) {
        const uint32_t kb = smem_u + Q_BYTES + buf * KV_PAIR;
        const uint32_t vb = kb + KV_TILE;
#pragma unroll
        for (int rep = 0; rep < 2; rep++) {
            const int row = ld_row + rep * 32;
            const size_t g = head_base + (size_t)(k0 + row) * 64 + ld_seg;
            const uint32_t so = row * ROWB + ld_seg * 2;
            CPA16(kb + so,       g_Khi + g);
            CPA16(kb + so + 128, g_Klo + g);
            CPA16(vb + so,       g_Vhi + g);
            CPA16(vb + so + 128, g_Vlo + g);
        }
        if (tid < 128) {
            const size_t wb = (mask_row_base + k0) >> 5;
            CPA8(smem_u + MS_OFF + buf * 1024 + tid * 8, (const char*)&g_maskbits[wb]);
        }
        CPA_COMMIT();
    };

    float oacc[8][4];
#pragma unroll
    for (int i = 0; i < 8; i++)
#pragma unroll
        for (int t = 0; t < 4; t++) oacc[i][t] = 0.f;
    float m0 = -INFINITY, m1 = -INFINITY, l0 = 0.f, l1 = 0.f;

    issue(0, 0);

    for (int t = 0; t < 32; t++) {
        const int buf = t & 1;
        if (t + 1 < 32) { issue((t + 1) << 6, buf ^ 1); CPA_WAIT1(); }
        else            { CPA_WAIT0(); }
        __syncthreads();

        const uint32_t kb_base = smem_u + Q_BYTES + buf * KV_PAIR + k_lane;
        const uint32_t vb_base = smem_u + Q_BYTES + buf * KV_PAIR + KV_TILE + v_lane;
        const unsigned long long* Mb = Ms + buf * 128;

        float sacc[8][4];
#pragma unroll
        for (int i = 0; i < 8; i++)
#pragma unroll
            for (int tt = 0; tt < 4; tt++) sacc[i][tt] = 0.f;

#pragma unroll
        for (int kk = 0; kk < 4; kk++) {
            uint32_t ah[4], al2[4];
            LDMX4(ah[0], ah[1], ah[2], ah[3], a_base + kk * 32);
            LDMX4(al2[0], al2[1], al2[2], al2[3], a_base + 128 + kk * 32);
#pragma unroll
            for (int g = 0; g < 4; g++) {
                uint32_t kh[4], kl[4];
                LDMX4(kh[0], kh[1], kh[2], kh[3], kb_base + g * (16 * ROWB) + kk * 32);
                MMA16816(sacc[2 * g + 0], ah, kh[0], kh[1]);
                MMA16816(sacc[2 * g + 1], ah, kh[2], kh[3]);
                MMA16816(sacc[2 * g + 0], al2, kh[0], kh[1]);
                MMA16816(sacc[2 * g + 1], al2, kh[2], kh[3]);
                LDMX4(kl[0], kl[1], kl[2], kl[3], kb_base + 128 + g * (16 * ROWB) + kk * 32);
                MMA16816(sacc[2 * g + 0], ah, kl[0], kl[1]);
                MMA16816(sacc[2 * g + 1], ah, kl[2], kl[3]);
            }
        }

        const int r0 = wq + (lane >> 2);
        const unsigned long long mw0 = Mb[r0];
        const unsigned long long mw1 = Mb[r0 + 8];
        const int cb0 = (lane & 3) << 1;
#pragma unroll
        for (int nb = 0; nb < 8; nb++) {
            int cb = (nb << 3) + cb0;
            sacc[nb][0] = ((mw0 >> cb) & 1ull)       ? -1e9f : sacc[nb][0] * 0.125f;
            sacc[nb][1] = ((mw0 >> (cb + 1)) & 1ull) ? -1e9f : sacc[nb][1] * 0.125f;
            sacc[nb][2] = ((mw1 >> cb) & 1ull)       ? -1e9f : sacc[nb][2] * 0.125f;
            sacc[nb][3] = ((mw1 >> (cb + 1)) & 1ull) ? -1e9f : sacc[nb][3] * 0.125f;
        }

        float mt0 = -1e30f, mt1 = -1e30f;
#pragma unroll
        for (int nb = 0; nb < 8; nb++) {
            mt0 = fmaxf(mt0, fmaxf(sacc[nb][0], sacc[nb][1]));
            mt1 = fmaxf(mt1, fmaxf(sacc[nb][2], sacc[nb][3]));
        }
        mt0 = fmaxf(mt0, __shfl_xor_sync(0xffffffffu, mt0, 1));
        mt0 = fmaxf(mt0, __shfl_xor_sync(0xffffffffu, mt0, 2));
        mt1 = fmaxf(mt1, __shfl_xor_sync(0xffffffffu, mt1, 1));
        mt1 = fmaxf(mt1, __shfl_xor_sync(0xffffffffu, mt1, 2));
        float mn0 = fmaxf(m0, mt0), mn1 = fmaxf(m1, mt1);
        float c0 = __expf(m0 - mn0), c1 = __expf(m1 - mn1);

        float ls0 = 0.f, ls1 = 0.f;
#pragma unroll
        for (int nb = 0; nb < 8; nb++) {
            sacc[nb][0] = __expf(sacc[nb][0] - mn0);
            sacc[nb][1] = __expf(sacc[nb][1] - mn0);
            sacc[nb][2] = __expf(sacc[nb][2] - mn1);
            sacc[nb][3] = __expf(sacc[nb][3] - mn1);
            ls0 += sacc[nb][0] + sacc[nb][1];
            ls1 += sacc[nb][2] + sacc[nb][3];
        }
        ls0 += __shfl_xor_sync(0xffffffffu, ls0, 1);
        ls0 += __shfl_xor_sync(0xffffffffu, ls0, 2);
        ls1 += __shfl_xor_sync(0xffffffffu, ls1, 1);
        ls1 += __shfl_xor_sync(0xffffffffu, ls1, 2);
        l0 = l0 * c0 + ls0; l1 = l1 * c1 + ls1;
        m0 = mn0; m1 = mn1;
#pragma unroll
        for (int nb = 0; nb < 8; nb++) {
            oacc[nb][0] *= c0; oacc[nb][1] *= c0;
            oacc[nb][2] *= c1; oacc[nb][3] *= c1;
        }

#pragma unroll
        for (int kk = 0; kk < 4; kk++) {
            uint32_t ph[4], pl[4];
            ph[0] = pack_bf2(sacc[2 * kk][0],     sacc[2 * kk][1]);
            ph[1] = pack_bf2(sacc[2 * kk][2],     sacc[2 * kk][3]);
            ph[2] = pack_bf2(sacc[2 * kk + 1][0], sacc[2 * kk + 1][1]);
            ph[3] = pack_bf2(sacc[2 * kk + 1][2], sacc[2 * kk + 1][3]);
            pl[0] = pack_lo2(sacc[2 * kk][0],     sacc[2 * kk][1]);
            pl[1] = pack_lo2(sacc[2 * kk][2],     sacc[2 * kk][3]);
            pl[2] = pack_lo2(sacc[2 * kk + 1][0], sacc[2 * kk + 1][1]);
            pl[3] = pack_lo2(sacc[2 * kk + 1][2], sacc[2 * kk + 1][3]);
#pragma unroll
            for (int nc = 0; nc < 4; nc++) {
                uint32_t vh[4], vl[4];
                LDMX4T(vh[0], vh[1], vh[2], vh[3], vb_base + nc * 32 + kk * (16 * ROWB));
                MMA16816(oacc[2 * nc + 0], ph, vh[0], vh[1]);
                MMA16816(oacc[2 * nc + 1], ph, vh[2], vh[3]);
                MMA16816(oacc[2 * nc + 0], pl, vh[0], vh[1]);
                MMA16816(oacc[2 * nc + 1], pl, vh[2], vh[3]);
                LDMX4T(vl[0], vl[1], vl[2], vl[3], vb_base + 128 + nc * 32 + kk * (16 * ROWB));
                MMA16816(oacc[2 * nc + 0], ph, vl[0], vl[1]);
                MMA16816(oacc[2 * nc + 1], ph, vl[2], vl[3]);
            }
        }
        __syncthreads();
    }

    {
        const float i0 = 1.0f / l0, i1 = 1.0f / l1;
        const int r0  = wq + (lane >> 2);
        const int cb0 = (lane & 3) << 1;
#pragma unroll
        for (int nb = 0; nb < 8; nb++) {
            int cb = (nb << 3) + cb0;
            float v0x = oacc[nb][0] * i0, v0y = oacc[nb][1] * i0;
            float v1x = oacc[nb][2] * i1, v1y = oacc[nb][3] * i1;
            *(uint32_t*)&Qs[r0][cb]          = pack_bf2(v0x, v0y);
            *(uint32_t*)&Qs[r0][64 + cb]     = pack_lo2(v0x, v0y);
            *(uint32_t*)&Qs[r0 + 8][cb]      = pack_bf2(v1x, v1y);
            *(uint32_t*)&Qs[r0 + 8][64 + cb] = pack_lo2(v1x, v1y);
        }
    }
    __syncthreads();
    for (int i = tid; i < 2048; i += 256) {
        const int row = i >> 4;
        const int seg = i & 15;
        __nv_bfloat16* dstrow = g_at3 + (size_t)(b * SS + q0 + row) * KP + h * 64;
        if (seg < 8) {
            uint4 v = *(uint4*)&Qs[row][seg * 8];
            *(uint4*)(dstrow + seg * 8)        = v;
            *(uint4*)(dstrow + 2048 + seg * 8) = v;
        } else {
            const int s = seg - 8;
            uint4 v = *(uint4*)&Qs[row][64 + s * 8];
            *(uint4*)(dstrow + 1024 + s * 8) = v;
        }
    }
}

// ---------------- LayerNorm ----------------
__global__ __launch_bounds__(256)
void ln_kernel(const float* __restrict__ y, const float* __restrict__ gam,
               const float* __restrict__ bet, float* __restrict__ out)
{
    const int row = blockIdx.x;
    const int tid = threadIdx.x;
    const float* yr = y + (size_t)row * 1024;
    float4 v = *(const float4*)(yr + (tid << 2));
    float s  = v.x + v.y + v.z + v.w;
    float ss = v.x * v.x + v.y * v.y + v.z * v.z + v.w * v.w;
#pragma unroll
    for (int off = 16; off; off >>= 1) {
        s  += __shfl_xor_sync(0xffffffffu, s,  off);
        ss += __shfl_xor_sync(0xffffffffu, ss, off);
    }
    __shared__ float red[16];
    __shared__ float stats[2];
    const int w = tid >> 5;
    if ((tid & 31) == 0) { red[w] = s; red[w + 8] = ss; }
    __syncthreads();
    if (tid == 0) {
        float ts = 0.f, tss = 0.f;
        for (int i = 0; i < 8; i++) { ts += red[i]; tss += red[i + 8]; }
        float mu  = ts * (1.0f / 1024.0f);
        float var = tss * (1.0f / 1024.0f) - mu * mu;
        stats[0] = mu;
        stats[1] = rsqrtf(var + 1e-5f);
    }
    __syncthreads();
    const float mu = stats[0], inv = stats[1];
    float4 g4 = *(const float4*)(gam + (tid << 2));
    float4 b4 = *(const float4*)(bet + (tid << 2));
    float4 rres;
    rres.x = (v.x - mu) * inv * g4.x + b4.x;
    rres.y = (v.y - mu) * inv * g4.y + b4.y;
    rres.z = (v.z - mu) * inv * g4.z + b4.z;
    rres.w = (v.w - mu) * inv * g4.w + b4.w;
    *(float4*)(out + (size_t)row * 1024 + (tid << 2)) = rres;
}

// ---------------- launch ----------------
extern "C" void kernel_launch(void* const* d_in, const int* in_sizes, int n_in,
                              void* d_out, int out_size)
{
    const float* x      = (const float*)d_in[0];
    const float* W_attn = (const float*)d_in[1];
    const float* b_attn = (const float*)d_in[2];
    const float* W_out  = (const float*)d_in[3];
    const float* b_out  = (const float*)d_in[4];
    const float* ln_g   = (const float*)d_in[5];
    const float* ln_b   = (const float*)d_in[6];
    const unsigned char* mask = (const unsigned char*)d_in[7];
    float* out = (float*)d_out;

    float* y;
    __nv_bfloat16 *x3, *at3, *wa3, *wo3;
    cudaGetSymbolAddress((void**)&y,    g_y);
    cudaGetSymbolAddress((void**)&x3,   g_x3);
    cudaGetSymbolAddress((void**)&at3,  g_at3);
    cudaGetSymbolAddress((void**)&wa3,  g_wa3);
    cudaGetSymbolAddress((void**)&wo3,  g_wo3);

    // 0) mask pack + operand conversions
    detect_mask_kernel<<<1, 1024>>>((const unsigned int*)mask);
    convert_mask_kernel<<<(BB * SS * SS / 32) / 256, 256>>>(mask);
    cvt_A3<<<(MROWS * 1024) / 1024, 256>>>(x, x3, 1024);
    cvt_B3<<<(1024 * 3072) / 1024, 256>>>(W_attn, wa3, 1024, 3072);
    cvt_B3<<<(1024 * 1024) / 1024, 256>>>(W_out, wo3, 1024, 1024);

    // 1) QKV projection: epilogue writes per-head hi/lo split (smem-staged)
    dim3 g1(3072 / 128, MROWS / 128);
    gemm_bf16<0><<<g1, 256>>>(x3, wa3, b_attn, nullptr, nullptr, MROWS, 3072, KP);

    // 2) attention (tensor cores, cp.async double-buffered K/V)
    cudaFuncSetAttribute(attn_mma, cudaFuncAttributeMaxDynamicSharedMemorySize, ATTN_SMEM);
    dim3 g2(SS / 128, BB * HH);
    attn_mma<<<g2, 256, ATTN_SMEM>>>();

    // 3) out projection + residual
    dim3 g3(DD / 128, MROWS / 128);
    gemm_bf16<1><<<g3, 256>>>(at3, wo3, b_out, x, y, MROWS, DD, KP);

    // 4) LayerNorm
    ln_kernel<<<MROWS, 256>>>(y, ln_g, ln_b, out);
}

// round 17
// speedup vs baseline: 1.0735x; 1.0074x over previous
#include <cuda_runtime.h>
#include <cuda_bf16.h>
#include <math.h>
#include <stdint.h>

#define BB 2
#define SS 2048
#define DD 1024
#define HH 16
#define MROWS (BB*SS)   // 4096
#define KP 3072         // 3*K split depth

// ---------------- scratch (no cudaMalloc allowed) ----------------
__device__ float g_y[(size_t)MROWS * DD];
__device__ int   g_mask_mode;
__device__ __align__(8) unsigned int g_maskbits[(size_t)BB * SS * SS / 32];
__device__ __nv_bfloat16 g_x3[(size_t)MROWS * KP];
__device__ __nv_bfloat16 g_at3[(size_t)MROWS * KP];
__device__ __nv_bfloat16 g_wa3[(size_t)KP * 3072];
__device__ __nv_bfloat16 g_wo3[(size_t)KP * 1024];
#define HSZ ((size_t)BB * HH * SS * 64)
__device__ __nv_bfloat16 g_Qhi[HSZ], g_Qlo[HSZ];
__device__ __nv_bfloat16 g_Khi[HSZ], g_Klo[HSZ];
__device__ __nv_bfloat16 g_Vhi[HSZ], g_Vlo[HSZ];

// ---------------- mask dtype detection ----------------
__global__ void detect_mask_kernel(const unsigned int* __restrict__ m)
{
    __shared__ int sfloat, shigh;
    if (threadIdx.x == 0) { sfloat = 0; shigh = 0; }
    __syncthreads();
    int ff = 0, fh = 0;
    for (int i = threadIdx.x; i < 8192; i += blockDim.x) {
        unsigned int w = m[i];
        if (w == 0x3F800000u) ff = 1;
        else if (w & 0xFFFFFF00u) fh = 1;
    }
    if (ff) atomicOr(&sfloat, 1);
    if (fh) atomicOr(&shigh, 1);
    __syncthreads();
    if (threadIdx.x == 0)
        g_mask_mode = sfloat ? 2 : (shigh ? 1 : 0);
}

// one thread -> one 32-bit mask word (32 positions), fully vectorized loads
__global__ __launch_bounds__(256)
void convert_mask_kernel(const unsigned char* __restrict__ mb)
{
    const int mode = g_mask_mode;
    const size_t w = (size_t)blockIdx.x * 256 + threadIdx.x;
    unsigned int bits = 0;
    if (mode == 1) {
        const uint4* p = (const uint4*)(mb + (w << 5));
        uint4 a = p[0], b = p[1];
        unsigned int arr[8] = {a.x, a.y, a.z, a.w, b.x, b.y, b.z, b.w};
#pragma unroll
        for (int i = 0; i < 8; i++) {
            unsigned int v = arr[i];
            bits |= ((v & 0x000000FFu) ? 1u : 0u) << (4 * i + 0);
            bits |= ((v & 0x0000FF00u) ? 1u : 0u) << (4 * i + 1);
            bits |= ((v & 0x00FF0000u) ? 1u : 0u) << (4 * i + 2);
            bits |= ((v & 0xFF000000u) ? 1u : 0u) << (4 * i + 3);
        }
    } else {
        const uint4* p = (const uint4*)mb + (w << 3);
#pragma unroll
        for (int i = 0; i < 8; i++) {
            uint4 v = p[i];
            const int base = i * 4;
            bits |= (v.x ? 1u : 0u) << (base + 0);
            bits |= (v.y ? 1u : 0u) << (base + 1);
            bits |= (v.z ? 1u : 0u) << (base + 2);
            bits |= (v.w ? 1u : 0u) << (base + 3);
        }
    }
    g_maskbits[w] = bits;
}

// ---------------- fused fp32 -> bf16x3 split conversions (one launch) ----------------
// blocks [0, 4096)        : A-split of x      -> g_x3  ([hi|lo|hi], K=1024)
// blocks [4096, 7168)     : B-split of W_attn -> g_wa3 (hi;hi;lo rows, N=3072)
// blocks [7168, 8192)     : B-split of W_out  -> g_wo3 (hi;hi;lo rows, N=1024)
__device__ __forceinline__ void split4(float4 v, __nv_bfloat16* h, __nv_bfloat16* l)
{
    h[0] = __float2bfloat16_rn(v.x); l[0] = __float2bfloat16_rn(v.x - __bfloat162float(h[0]));
    h[1] = __float2bfloat16_rn(v.y); l[1] = __float2bfloat16_rn(v.y - __bfloat162float(h[1]));
    h[2] = __float2bfloat16_rn(v.z); l[2] = __float2bfloat16_rn(v.z - __bfloat162float(h[2]));
    h[3] = __float2bfloat16_rn(v.w); l[3] = __float2bfloat16_rn(v.w - __bfloat162float(h[3]));
}

__global__ __launch_bounds__(256)
void cvt_all(const float* __restrict__ x, const float* __restrict__ Wa,
             const float* __restrict__ Wo)
{
    const int bi = blockIdx.x;
    __nv_bfloat16 h[4], l[4];
    if (bi < 4096) {
        // A-split: x [4096 x 1024]
        size_t i = ((size_t)bi * 256 + threadIdx.x) * 4;
        const int K = 1024;
        int m = (int)(i / K), k = (int)(i % K);
        float4 v = *(const float4*)(x + i);
        split4(v, h, l);
        __nv_bfloat16* row = g_x3 + (size_t)m * (3 * K);
        *(uint2*)(row + k)         = *(uint2*)h;
        *(uint2*)(row + K + k)     = *(uint2*)l;
        *(uint2*)(row + 2 * K + k) = *(uint2*)h;
    } else if (bi < 7168) {
        // B-split: W_attn [1024 x 3072]
        size_t i = ((size_t)(bi - 4096) * 256 + threadIdx.x) * 4;
        const int K = 1024, N = 3072;
        int r = (int)(i / N), c = (int)(i % N);
        float4 v = *(const float4*)(Wa + i);
        split4(v, h, l);
        *(uint2*)(g_wa3 + (size_t)r * N + c)           = *(uint2*)h;
        *(uint2*)(g_wa3 + (size_t)(K + r) * N + c)     = *(uint2*)h;
        *(uint2*)(g_wa3 + (size_t)(2 * K + r) * N + c) = *(uint2*)l;
    } else {
        // B-split: W_out [1024 x 1024]
        size_t i = ((size_t)(bi - 7168) * 256 + threadIdx.x) * 4;
        const int K = 1024, N = 1024;
        int r = (int)(i / N), c = (int)(i % N);
        float4 v = *(const float4*)(Wo + i);
        split4(v, h, l);
        *(uint2*)(g_wo3 + (size_t)r * N + c)           = *(uint2*)h;
        *(uint2*)(g_wo3 + (size_t)(K + r) * N + c)     = *(uint2*)h;
        *(uint2*)(g_wo3 + (size_t)(2 * K + r) * N + c) = *(uint2*)l;
    }
}

// ---------------- fp32 -> bf16x3 A-split (used for attention output path) ----------------
__global__ __launch_bounds__(256)
void cvt_A3(const float* __restrict__ A, __nv_bfloat16* __restrict__ out, int K)
{
    size_t i = ((size_t)blockIdx.x * 256 + threadIdx.x) * 4;
    int m = (int)(i / K), k = (int)(i % K);
    float4 v = *(const float4*)(A + i);
    __nv_bfloat16 h[4], l[4];
    split4(v, h, l);
    __nv_bfloat16* row = out + (size_t)m * (3 * K);
    *(uint2*)(row + k)         = *(uint2*)h;
    *(uint2*)(row + K + k)     = *(uint2*)l;
    *(uint2*)(row + 2 * K + k) = *(uint2*)h;
}

// ---------------- MMA / cp.async macros ----------------
#define LDMX4(R0,R1,R2,R3,addr) \
    asm volatile("ldmatrix.sync.aligned.m8n8.x4.shared.b16 {%0,%1,%2,%3}, [%4];" \
        : "=r"(R0),"=r"(R1),"=r"(R2),"=r"(R3) : "r"(addr))
#define LDMX4T(R0,R1,R2,R3,addr) \
    asm volatile("ldmatrix.sync.aligned.m8n8.x4.trans.shared.b16 {%0,%1,%2,%3}, [%4];" \
        : "=r"(R0),"=r"(R1),"=r"(R2),"=r"(R3) : "r"(addr))
#define MMA16816(d, a, b0, b1) \
    asm volatile("mma.sync.aligned.m16n8k16.row.col.f32.bf16.bf16.f32 " \
        "{%0,%1,%2,%3}, {%4,%5,%6,%7}, {%8,%9}, {%0,%1,%2,%3};" \
        : "+f"(d[0]),"+f"(d[1]),"+f"(d[2]),"+f"(d[3]) \
        : "r"(a[0]),"r"(a[1]),"r"(a[2]),"r"(a[3]), "r"(b0),"r"(b1))
#define CPA16(saddr, gptr) \
    asm volatile("cp.async.cg.shared.global [%0], [%1], 16;" :: "r"(saddr), "l"(gptr))
#define CPA8(saddr, gptr) \
    asm volatile("cp.async.ca.shared.global [%0], [%1], 8;" :: "r"(saddr), "l"(gptr))
#define CPA_COMMIT() asm volatile("cp.async.commit_group;")
#define CPA_WAIT1()  asm volatile("cp.async.wait_group 1;")
#define CPA_WAIT0()  asm volatile("cp.async.wait_group 0;")

__device__ __forceinline__ uint32_t pack_bf2(float a, float b) {
    __nv_bfloat162 t = __floats2bfloat162_rn(a, b);
    return *(uint32_t*)&t;
}
__device__ __forceinline__ uint32_t pack_lo2(float a, float b) {
    float ha = __bfloat162float(__float2bfloat16_rn(a));
    float hb = __bfloat162float(__float2bfloat16_rn(b));
    return pack_bf2(a - ha, b - hb);
}

// ---------------- bf16 tensor-core GEMM, double-buffered smem ----------------
// EPI=0: epilogue stages per-head Q/K/V hi/lo split through smem (QKV proj)
// EPI=1: epilogue writes fp32 C with bias + residual (out proj)
#define A_OFF 0
#define B_OFF 20480
#define ABUF (128*40*2)
#define BBUF (32*136*2)
#define GEMM_SMEM 37888

template<int EPI>
__global__ __launch_bounds__(256)
void gemm_bf16(const __nv_bfloat16* __restrict__ A, const __nv_bfloat16* __restrict__ B,
               const float* __restrict__ bias, const float* __restrict__ resid,
               float* __restrict__ C, int M, int N, int Kp)
{
    __shared__ __align__(16) char smraw[GEMM_SMEM];
    __nv_bfloat16 (*As)[128][40]  = (__nv_bfloat16(*)[128][40])(smraw + A_OFF);
    __nv_bfloat16 (*Bs)[32][136]  = (__nv_bfloat16(*)[32][136])(smraw + B_OFF);

    const int tid  = threadIdx.x;
    const int lane = tid & 31;
    const int wid  = tid >> 5;
    const int wm   = wid & 3;
    const int wn   = wid >> 2;
    const int bm = blockIdx.y * 128, bn = blockIdx.x * 128;

    const int a_chunk = tid & 3;
    const int a_row   = tid >> 2;
    const int b_chunk = tid & 15;
    const int b_row   = tid >> 4;

    const __nv_bfloat16* Ag = A + (size_t)bm * Kp;
    const __nv_bfloat16* Bg = B + bn;

    uint4 ar0 = *(const uint4*)(Ag + (size_t)a_row * Kp + a_chunk * 8);
    uint4 ar1 = *(const uint4*)(Ag + (size_t)(a_row + 64) * Kp + a_chunk * 8);
    uint4 br0 = *(const uint4*)(Bg + (size_t)b_row * N + b_chunk * 8);
    uint4 br1 = *(const uint4*)(Bg + (size_t)(b_row + 16) * N + b_chunk * 8);
    *(uint4*)&As[0][a_row][a_chunk * 8]      = ar0;
    *(uint4*)&As[0][a_row + 64][a_chunk * 8] = ar1;
    *(uint4*)&Bs[0][b_row][b_chunk * 8]      = br0;
    *(uint4*)&Bs[0][b_row + 16][b_chunk * 8] = br1;
    __syncthreads();

    float acc[2][8][4];
#pragma unroll
    for (int i = 0; i < 2; i++)
#pragma unroll
        for (int j = 0; j < 8; j++)
#pragma unroll
            for (int t = 0; t < 4; t++) acc[i][j][t] = 0.f;

    uint32_t a_base[2], b_base[4];
#pragma unroll
    for (int mi = 0; mi < 2; mi++)
        a_base[mi] = (uint32_t)__cvta_generic_to_shared(
            &As[0][wm * 32 + mi * 16 + (lane & 15)][(lane >> 4) * 8]);
#pragma unroll
    for (int nc = 0; nc < 4; nc++)
        b_base[nc] = (uint32_t)__cvta_generic_to_shared(
            &Bs[0][lane & 15][wn * 64 + nc * 16 + (lane >> 4) * 8]);

    for (int k0 = 0; k0 < Kp; k0 += 32) {
        const int buf = (k0 >> 5) & 1;
        const uint32_t ao = buf * ABUF;
        const uint32_t bo = buf * BBUF;
        const bool more = (k0 + 32 < Kp);

        if (more) {
            const __nv_bfloat16* Ag2 = Ag + k0 + 32;
            const __nv_bfloat16* Bg2 = Bg + (size_t)(k0 + 32) * N;
            ar0 = *(const uint4*)(Ag2 + (size_t)a_row * Kp + a_chunk * 8);
            ar1 = *(const uint4*)(Ag2 + (size_t)(a_row + 64) * Kp + a_chunk * 8);
            br0 = *(const uint4*)(Bg2 + (size_t)b_row * N + b_chunk * 8);
            br1 = *(const uint4*)(Bg2 + (size_t)(b_row + 16) * N + b_chunk * 8);
        }

#pragma unroll
        for (int kk = 0; kk < 2; kk++) {
            uint32_t af[2][4], bf[4][4];
#pragma unroll
            for (int mi = 0; mi < 2; mi++)
                LDMX4(af[mi][0], af[mi][1], af[mi][2], af[mi][3],
                      a_base[mi] + ao + kk * 32);
#pragma unroll
            for (int nc = 0; nc < 4; nc++)
                LDMX4T(bf[nc][0], bf[nc][1], bf[nc][2], bf[nc][3],
                       b_base[nc] + bo + kk * 16 * 272);
#pragma unroll
            for (int mi = 0; mi < 2; mi++)
#pragma unroll
                for (int nc = 0; nc < 4; nc++) {
                    MMA16816(acc[mi][nc * 2 + 0], af[mi], bf[nc][0], bf[nc][1]);
                    MMA16816(acc[mi][nc * 2 + 1], af[mi], bf[nc][2], bf[nc][3]);
                }
        }

        if (more) {
            const int nb = buf ^ 1;
            *(uint4*)&As[nb][a_row][a_chunk * 8]      = ar0;
            *(uint4*)&As[nb][a_row + 64][a_chunk * 8] = ar1;
            *(uint4*)&Bs[nb][b_row][b_chunk * 8]      = br0;
            *(uint4*)&Bs[nb][b_row + 16][b_chunk * 8] = br1;
        }
        __syncthreads();
    }

    const int row_base = bm + wm * 32 + (lane >> 2);
    const int col_base = bn + wn * 64 + (lane & 3) * 2;

    if (EPI == 1) {
#pragma unroll
        for (int mi = 0; mi < 2; mi++) {
#pragma unroll
            for (int ni = 0; ni < 8; ni++) {
                const int c  = col_base + ni * 8;
                const int r0 = row_base + mi * 16;
                const float bx = bias[c], by = bias[c + 1];
                float2 v0 = make_float2(acc[mi][ni][0] + bx, acc[mi][ni][1] + by);
                float2 v1 = make_float2(acc[mi][ni][2] + bx, acc[mi][ni][3] + by);
                if (resid) {
                    float2 r0v = *(const float2*)(resid + (size_t)r0 * N + c);
                    float2 r1v = *(const float2*)(resid + (size_t)(r0 + 8) * N + c);
                    v0.x += r0v.x; v0.y += r0v.y;
                    v1.x += r1v.x; v1.y += r1v.y;
                }
                *(float2*)(C + (size_t)r0 * N + c)       = v0;
                *(float2*)(C + (size_t)(r0 + 8) * N + c) = v1;
            }
        }
    } else {
        // QKV: stage hi (pass 0) then lo (pass 1) through smem, stream coalesced
        __nv_bfloat16 (*St)[136] = (__nv_bfloat16(*)[136])smraw;
        const int lr0 = wm * 32 + (lane >> 2);
        const int lc0 = wn * 64 + ((lane & 3) << 1);
#pragma unroll
        for (int pass = 0; pass < 2; pass++) {
            if (pass) __syncthreads();
#pragma unroll
            for (int mi = 0; mi < 2; mi++) {
#pragma unroll
                for (int ni = 0; ni < 8; ni++) {
                    const int c = col_base + ni * 8;
                    const float bx = bias[c], by = bias[c + 1];
                    float v0x = acc[mi][ni][0] + bx, v0y = acc[mi][ni][1] + by;
                    float v1x = acc[mi][ni][2] + bx, v1y = acc[mi][ni][3] + by;
                    uint32_t w0, w1;
                    if (pass == 0) { w0 = pack_bf2(v0x, v0y); w1 = pack_bf2(v1x, v1y); }
                    else           { w0 = pack_lo2(v0x, v0y); w1 = pack_lo2(v1x, v1y); }
                    const int lc = lc0 + ni * 8;
                    *(uint32_t*)&St[lr0 + mi * 16][lc]     = w0;
                    *(uint32_t*)&St[lr0 + mi * 16 + 8][lc] = w1;
                }
            }
            __syncthreads();
            for (int i = tid; i < 2048; i += 256) {
                const int row = i >> 4, seg = i & 15;
                const int rg = bm + row;
                const int cg = bn + seg * 8;
                const int sec = cg >> 10;
                const int h   = (cg & 1023) >> 6;
                const int d   = cg & 63;
                __nv_bfloat16* base;
                if (pass == 0) base = (sec == 0) ? g_Qhi : (sec == 1) ? g_Khi : g_Vhi;
                else           base = (sec == 0) ? g_Qlo : (sec == 1) ? g_Klo : g_Vlo;
                size_t dst = (((size_t)((rg >> 11) * HH + h) * SS + (rg & 2047)) << 6) + d;
                *(uint4*)(base + dst) = *(uint4*)&St[row][seg * 8];
            }
        }
    }
}

// ---------------- tensor-core flash attention, 128-q tile, register-P ----------------
#define ATTN_PAD 136
#define ROWB (ATTN_PAD*2)            // 272 bytes per row
#define Q_BYTES  (128*ROWB)          // 34816
#define KV_TILE  (64*ROWB)           // 17408
#define KV_PAIR  (2*KV_TILE)         // 34816
#define MS_OFF   (Q_BYTES + 2*KV_PAIR)   // 104448
#define ATTN_SMEM (MS_OFF + 2*128*8)     // 106496

__global__ __launch_bounds__(256, 2)
void attn_mma()
{
    extern __shared__ char smc[];
    __nv_bfloat16 (*Qs)[ATTN_PAD] = (__nv_bfloat16(*)[ATTN_PAD])(smc);
    unsigned long long* Ms = (unsigned long long*)(smc + MS_OFF);
    const uint32_t smem_u = (uint32_t)__cvta_generic_to_shared(smc);

    const int tid  = threadIdx.x;
    const int lane = tid & 31;
    const int wid  = tid >> 5;
    const int wq   = wid << 4;
    const int b  = blockIdx.y >> 4;
    const int h  = blockIdx.y & 15;
    const int q0 = blockIdx.x << 7;
    const size_t head_base = ((size_t)(b * HH + h) * SS) << 6;

    for (int i = tid; i < 1024; i += 256) {
        int row = i >> 3, seg = (i & 7) << 3;
        size_t g = head_base + (size_t)(q0 + row) * 64 + seg;
        *(uint4*)&Qs[row][seg]      = *(const uint4*)(g_Qhi + g);
        *(uint4*)&Qs[row][64 + seg] = *(const uint4*)(g_Qlo + g);
    }

    const uint32_t a_base = (uint32_t)__cvta_generic_to_shared(
        &Qs[wq + (lane & 15)][(lane >> 4) * 8]);
    const int mat = lane >> 3, rr = lane & 7;
    const uint32_t k_lane = (uint32_t)((((mat >> 1) << 3) + rr) * ROWB + (mat & 1) * 16);
    const uint32_t v_lane = (uint32_t)((lane & 15) * ROWB + (lane >> 4) * 16);

    const int ld_row = tid >> 3, ld_seg = (tid & 7) << 3;
    const size_t mask_row_base = (size_t)(b * SS + q0 + tid) * SS;

    auto issue = [&](int k0, int buf) {
        const uint32_t kb = smem_u + Q_BYTES + buf * KV_PAIR;
        const uint32_t vb = kb + KV_TILE;
#pragma unroll
        for (int rep = 0; rep < 2; rep++) {
            const int row = ld_row + rep * 32;
            const size_t g = head_base + (size_t)(k0 + row) * 64 + ld_seg;
            const uint32_t so = row * ROWB + ld_seg * 2;
            CPA16(kb + so,       g_Khi + g);
            CPA16(kb + so + 128, g_Klo + g);
            CPA16(vb + so,       g_Vhi + g);
            CPA16(vb + so + 128, g_Vlo + g);
        }
        if (tid < 128) {
            const size_t wb = (mask_row_base + k0) >> 5;
            CPA8(smem_u + MS_OFF + buf * 1024 + tid * 8, (const char*)&g_maskbits[wb]);
        }
        CPA_COMMIT();
    };

    float oacc[8][4];
#pragma unroll
    for (int i = 0; i < 8; i++)
#pragma unroll
        for (int t = 0; t < 4; t++) oacc[i][t] = 0.f;
    float m0 = -INFINITY, m1 = -INFINITY, l0 = 0.f, l1 = 0.f;

    issue(0, 0);

    for (int t = 0; t < 32; t++) {
        const int buf = t & 1;
        if (t + 1 < 32) { issue((t + 1) << 6, buf ^ 1); CPA_WAIT1(); }
        else            { CPA_WAIT0(); }
        __syncthreads();

        const uint32_t kb_base = smem_u + Q_BYTES + buf * KV_PAIR + k_lane;
        const uint32_t vb_base = smem_u + Q_BYTES + buf * KV_PAIR + KV_TILE + v_lane;
        const unsigned long long* Mb = Ms + buf * 128;

        float sacc[8][4];
#pragma unroll
        for (int i = 0; i < 8; i++)
#pragma unroll
            for (int tt = 0; tt < 4; tt++) sacc[i][tt] = 0.f;

#pragma unroll
        for (int kk = 0; kk < 4; kk++) {
            uint32_t ah[4], al2[4];
            LDMX4(ah[0], ah[1], ah[2], ah[3], a_base + kk * 32);
            LDMX4(al2[0], al2[1], al2[2], al2[3], a_base + 128 + kk * 32);
#pragma unroll
            for (int g = 0; g < 4; g++) {
                uint32_t kh[4], kl[4];
                LDMX4(kh[0], kh[1], kh[2], kh[3], kb_base + g * (16 * ROWB) + kk * 32);
                MMA16816(sacc[2 * g + 0], ah, kh[0], kh[1]);
                MMA16816(sacc[2 * g + 1], ah, kh[2], kh[3]);
                MMA16816(sacc[2 * g + 0], al2, kh[0], kh[1]);
                MMA16816(sacc[2 * g + 1], al2, kh[2], kh[3]);
                LDMX4(kl[0], kl[1], kl[2], kl[3], kb_base + 128 + g * (16 * ROWB) + kk * 32);
                MMA16816(sacc[2 * g + 0], ah, kl[0], kl[1]);
                MMA16816(sacc[2 * g + 1], ah, kl[2], kl[3]);
            }
        }

        const int r0 = wq + (lane >> 2);
        const unsigned long long mw0 = Mb[r0];
        const unsigned long long mw1 = Mb[r0 + 8];
        const int cb0 = (lane & 3) << 1;
#pragma unroll
        for (int nb = 0; nb < 8; nb++) {
            int cb = (nb << 3) + cb0;
            sacc[nb][0] = ((mw0 >> cb) & 1ull)       ? -1e9f : sacc[nb][0] * 0.125f;
            sacc[nb][1] = ((mw0 >> (cb + 1)) & 1ull) ? -1e9f : sacc[nb][1] * 0.125f;
            sacc[nb][2] = ((mw1 >> cb) & 1ull)       ? -1e9f : sacc[nb][2] * 0.125f;
            sacc[nb][3] = ((mw1 >> (cb + 1)) & 1ull) ? -1e9f : sacc[nb][3] * 0.125f;
        }

        float mt0 = -1e30f, mt1 = -1e30f;
#pragma unroll
        for (int nb = 0; nb < 8; nb++) {
            mt0 = fmaxf(mt0, fmaxf(sacc[nb][0], sacc[nb][1]));
            mt1 = fmaxf(mt1, fmaxf(sacc[nb][2], sacc[nb][3]));
        }
        mt0 = fmaxf(mt0, __shfl_xor_sync(0xffffffffu, mt0, 1));
        mt0 = fmaxf(mt0, __shfl_xor_sync(0xffffffffu, mt0, 2));
        mt1 = fmaxf(mt1, __shfl_xor_sync(0xffffffffu, mt1, 1));
        mt1 = fmaxf(mt1, __shfl_xor_sync(0xffffffffu, mt1, 2));
        float mn0 = fmaxf(m0, mt0), mn1 = fmaxf(m1, mt1);
        float c0 = __expf(m0 - mn0), c1 = __expf(m1 - mn1);

        float ls0 = 0.f, ls1 = 0.f;
#pragma unroll
        for (int nb = 0; nb < 8; nb++) {
            sacc[nb][0] = __expf(sacc[nb][0] - mn0);
            sacc[nb][1] = __expf(sacc[nb][1] - mn0);
            sacc[nb][2] = __expf(sacc[nb][2] - mn1);
            sacc[nb][3] = __expf(sacc[nb][3] - mn1);
            ls0 += sacc[nb][0] + sacc[nb][1];
            ls1 += sacc[nb][2] + sacc[nb][3];
        }
        ls0 += __shfl_xor_sync(0xffffffffu, ls0, 1);
        ls0 += __shfl_xor_sync(0xffffffffu, ls0, 2);
        ls1 += __shfl_xor_sync(0xffffffffu, ls1, 1);
        ls1 += __shfl_xor_sync(0xffffffffu, ls1, 2);
        l0 = l0 * c0 + ls0; l1 = l1 * c1 + ls1;
        m0 = mn0; m1 = mn1;
#pragma unroll
        for (int nb = 0; nb < 8; nb++) {
            oacc[nb][0] *= c0; oacc[nb][1] *= c0;
            oacc[nb][2] *= c1; oacc[nb][3] *= c1;
        }

#pragma unroll
        for (int kk = 0; kk < 4; kk++) {
            uint32_t ph[4], pl[4];
            ph[0] = pack_bf2(sacc[2 * kk][0],     sacc[2 * kk][1]);
            ph[1] = pack_bf2(sacc[2 * kk][2],     sacc[2 * kk][3]);
            ph[2] = pack_bf2(sacc[2 * kk + 1][0], sacc[2 * kk + 1][1]);
            ph[3] = pack_bf2(sacc[2 * kk + 1][2], sacc[2 * kk + 1][3]);
            pl[0] = pack_lo2(sacc[2 * kk][0],     sacc[2 * kk][1]);
            pl[1] = pack_lo2(sacc[2 * kk][2],     sacc[2 * kk][3]);
            pl[2] = pack_lo2(sacc[2 * kk + 1][0], sacc[2 * kk + 1][1]);
            pl[3] = pack_lo2(sacc[2 * kk + 1][2], sacc[2 * kk + 1][3]);
#pragma unroll
            for (int nc = 0; nc < 4; nc++) {
                uint32_t vh[4], vl[4];
                LDMX4T(vh[0], vh[1], vh[2], vh[3], vb_base + nc * 32 + kk * (16 * ROWB));
                MMA16816(oacc[2 * nc + 0], ph, vh[0], vh[1]);
                MMA16816(oacc[2 * nc + 1], ph, vh[2], vh[3]);
                MMA16816(oacc[2 * nc + 0], pl, vh[0], vh[1]);
                MMA16816(oacc[2 * nc + 1], pl, vh[2], vh[3]);
                LDMX4T(vl[0], vl[1], vl[2], vl[3], vb_base + 128 + nc * 32 + kk * (16 * ROWB));
                MMA16816(oacc[2 * nc + 0], ph, vl[0], vl[1]);
                MMA16816(oacc[2 * nc + 1], ph, vl[2], vl[3]);
            }
        }
        __syncthreads();
    }

    {
        const float i0 = 1.0f / l0, i1 = 1.0f / l1;
        const int r0  = wq + (lane >> 2);
        const int cb0 = (lane & 3) << 1;
#pragma unroll
        for (int nb = 0; nb < 8; nb++) {
            int cb = (nb << 3) + cb0;
            float v0x = oacc[nb][0] * i0, v0y = oacc[nb][1] * i0;
            float v1x = oacc[nb][2] * i1, v1y = oacc[nb][3] * i1;
            *(uint32_t*)&Qs[r0][cb]          = pack_bf2(v0x, v0y);
            *(uint32_t*)&Qs[r0][64 + cb]     = pack_lo2(v0x, v0y);
            *(uint32_t*)&Qs[r0 + 8][cb]      = pack_bf2(v1x, v1y);
            *(uint32_t*)&Qs[r0 + 8][64 + cb] = pack_lo2(v1x, v1y);
        }
    }
    __syncthreads();
    for (int i = tid; i < 2048; i += 256) {
        const int row = i >> 4;
        const int seg = i & 15;
        __nv_bfloat16* dstrow = g_at3 + (size_t)(b * SS + q0 + row) * KP + h * 64;
        if (seg < 8) {
            uint4 v = *(uint4*)&Qs[row][seg * 8];
            *(uint4*)(dstrow + seg * 8)        = v;
            *(uint4*)(dstrow + 2048 + seg * 8) = v;
        } else {
            const int s = seg - 8;
            uint4 v = *(uint4*)&Qs[row][64 + s * 8];
            *(uint4*)(dstrow + 1024 + s * 8) = v;
        }
    }
}

// ---------------- LayerNorm ----------------
__global__ __launch_bounds__(256)
void ln_kernel(const float* __restrict__ y, const float* __restrict__ gam,
               const float* __restrict__ bet, float* __restrict__ out)
{
    const int row = blockIdx.x;
    const int tid = threadIdx.x;
    const float* yr = y + (size_t)row * 1024;
    float4 v = *(const float4*)(yr + (tid << 2));
    float s  = v.x + v.y + v.z + v.w;
    float ss = v.x * v.x + v.y * v.y + v.z * v.z + v.w * v.w;
#pragma unroll
    for (int off = 16; off; off >>= 1) {
        s  += __shfl_xor_sync(0xffffffffu, s,  off);
        ss += __shfl_xor_sync(0xffffffffu, ss, off);
    }
    __shared__ float red[16];
    __shared__ float stats[2];
    const int w = tid >> 5;
    if ((tid & 31) == 0) { red[w] = s; red[w + 8] = ss; }
    __syncthreads();
    if (tid == 0) {
        float ts = 0.f, tss = 0.f;
        for (int i = 0; i < 8; i++) { ts += red[i]; tss += red[i + 8]; }
        float mu  = ts * (1.0f / 1024.0f);
        float var = tss * (1.0f / 1024.0f) - mu * mu;
        stats[0] = mu;
        stats[1] = rsqrtf(var + 1e-5f);
    }
    __syncthreads();
    const float mu = stats[0], inv = stats[1];
    float4 g4 = *(const float4*)(gam + (tid << 2));
    float4 b4 = *(const float4*)(bet + (tid << 2));
    float4 rres;
    rres.x = (v.x - mu) * inv * g4.x + b4.x;
    rres.y = (v.y - mu) * inv * g4.y + b4.y;
    rres.z = (v.z - mu) * inv * g4.z + b4.z;
    rres.w = (v.w - mu) * inv * g4.w + b4.w;
    *(float4*)(out + (size_t)row * 1024 + (tid << 2)) = rres;
}

// ---------------- launch ----------------
extern "C" void kernel_launch(void* const* d_in, const int* in_sizes, int n_in,
                              void* d_out, int out_size)
{
    const float* x      = (const float*)d_in[0];
    const float* W_attn = (const float*)d_in[1];
    const float* b_attn = (const float*)d_in[2];
    const float* W_out  = (const float*)d_in[3];
    const float* b_out  = (const float*)d_in[4];
    const float* ln_g   = (const float*)d_in[5];
    const float* ln_b   = (const float*)d_in[6];
    const unsigned char* mask = (const unsigned char*)d_in[7];
    float* out = (float*)d_out;

    float* y;
    __nv_bfloat16 *x3, *at3, *wa3, *wo3;
    cudaGetSymbolAddress((void**)&y,    g_y);
    cudaGetSymbolAddress((void**)&x3,   g_x3);
    cudaGetSymbolAddress((void**)&at3,  g_at3);
    cudaGetSymbolAddress((void**)&wa3,  g_wa3);
    cudaGetSymbolAddress((void**)&wo3,  g_wo3);

    // 0) mask pack + fused operand conversions (one launch)
    detect_mask_kernel<<<1, 1024>>>((const unsigned int*)mask);
    convert_mask_kernel<<<(BB * SS * SS / 32) / 256, 256>>>(mask);
    cvt_all<<<8192, 256>>>(x, W_attn, W_out);

    // 1) QKV projection: epilogue writes per-head hi/lo split (smem-staged)
    dim3 g1(3072 / 128, MROWS / 128);
    gemm_bf16<0><<<g1, 256>>>(x3, wa3, b_attn, nullptr, nullptr, MROWS, 3072, KP);

    // 2) attention (tensor cores, cp.async double-buffered K/V)
    cudaFuncSetAttribute(attn_mma, cudaFuncAttributeMaxDynamicSharedMemorySize, ATTN_SMEM);
    dim3 g2(SS / 128, BB * HH);
    attn_mma<<<g2, 256, ATTN_SMEM>>>();

    // 3) out projection + residual
    dim3 g3(DD / 128, MROWS / 128);
    gemm_bf16<1><<<g3, 256>>>(at3, wo3, b_out, x, y, MROWS, DD, KP);

    // 4) LayerNorm
    ln_kernel<<<MROWS, 256>>>(y, ln_g, ln_b, out);
}